// round 1
// baseline (speedup 1.0000x reference)
#include <cuda_runtime.h>
#include <math.h>

#define NN 100000
#define EE 1600000
#define DD 256
#define HH 512
#define LL 5

// ---------------- device scratch (no allocs allowed) ----------------
__device__ float g_h[(size_t)NN * DD];     // node features (102.4 MB)
__device__ float g_agg[(size_t)NN * DD];   // aggregation buffer; reused as z2 (102.4 MB)
__device__ float g_t1[(size_t)NN * HH];    // hidden activations (204.8 MB)
__device__ float g_sum[HH];
__device__ float g_sumsq[HH];
__device__ float g_a[HH];                  // BN scale
__device__ float g_bc[HH];                 // BN shift

// ---------------- f32x2 packed FMA helpers ----------------
__device__ __forceinline__ unsigned long long ffma2(unsigned long long a,
                                                    unsigned long long b,
                                                    unsigned long long c) {
    unsigned long long d;
    asm("fma.rn.f32x2 %0, %1, %2, %3;" : "=l"(d) : "l"(a), "l"(b), "l"(c));
    return d;
}
__device__ __forceinline__ unsigned long long bcast2(float x) {
    unsigned long long r;
    asm("mov.b64 %0, {%1, %1};" : "=l"(r) : "f"(x));
    return r;
}

// ---------------- init: h = node_emb[x] ----------------
__global__ void k_init_h(const int* __restrict__ x, const float* __restrict__ emb) {
    int i = blockIdx.x;
    int d = threadIdx.x;
    g_h[(size_t)i * DD + d] = emb[(size_t)x[i] * DD + d];
}

// ---------------- zero kernels ----------------
__global__ void k_zero_agg() {
    size_t i = (size_t)blockIdx.x * blockDim.x + threadIdx.x;
    float4 z = make_float4(0.f, 0.f, 0.f, 0.f);
    ((float4*)g_agg)[i] = z;
}
__global__ void k_zero_stats() {
    int i = blockIdx.x * blockDim.x + threadIdx.x;
    if (i < HH) { g_sum[i] = 0.f; g_sumsq[i] = 0.f; }
}

// ---------------- edge phase: agg[dst] += relu(h[src] + attr@We + be) ----------------
#define EPB 256
__global__ void k_edge(const int* __restrict__ ei, const float* __restrict__ attr,
                       const float* __restrict__ We, const float* __restrict__ be, int E) {
    __shared__ float We_s[7 * DD];
    __shared__ float be_s[DD];
    __shared__ float at_s[EPB * 7];
    __shared__ int src_s[EPB];
    __shared__ int dst_s[EPB];
    int tid = threadIdx.x;
    int base = blockIdx.x * EPB;

    for (int i = tid; i < 7 * DD; i += 256) We_s[i] = We[i];
    be_s[tid] = be[tid];
    int cnt = min(EPB, E - base);
    for (int i = tid; i < cnt * 7; i += 256) at_s[i] = attr[(size_t)base * 7 + i];
    if (tid < cnt) {
        src_s[tid] = ei[base + tid];
        dst_s[tid] = ei[(size_t)E + base + tid];
    }
    __syncthreads();

    int d = tid;
    #pragma unroll 4
    for (int e = 0; e < cnt; e++) {
        float embv = be_s[d];
        #pragma unroll
        for (int k = 0; k < 7; k++) embv = fmaf(at_s[e * 7 + k], We_s[k * DD + d], embv);
        float hv = g_h[(size_t)src_s[e] * DD + d];
        float m = fmaxf(hv + embv, 0.f);
        atomicAdd(&g_agg[(size_t)dst_s[e] * DD + d], m);
    }
}

// ---------------- GEMM: C = f(A) @ B ----------------
// MODE 0: A[i,k] = (1+eps)*h[i,k] + agg[i,k];  C -> g_t1   (K=DD, NC=HH)
// MODE 1: A[i,k] = relu(t1[i,k]*g_a[k]+g_bc[k]); C -> g_agg (K=HH, NC=DD)
template <int MODE, int K, int NC>
__global__ void __launch_bounds__(256, 2)
k_gemm(const float* __restrict__ B, const float* __restrict__ epsp, int M) {
    const int BM = 128, BN = 128, BK = 16;
    __shared__ float As[BK][BM + 4];
    __shared__ float Bs[BK][BN];

    int tid = threadIdx.x;
    int tx = tid % 16, ty = tid / 16;
    int brow = blockIdx.y * BM, bcol = blockIdx.x * BN;

    int ar = tid / 4, ak = (tid % 4) * 4;   // A-loader: rows ar, ar+64; k in [ak,ak+4)
    int br = tid / 32, bc = (tid % 32) * 4; // B-loader: rows br, br+8; cols [bc,bc+4)

    unsigned long long acc[8][4];
    #pragma unroll
    for (int i = 0; i < 8; i++)
        #pragma unroll
        for (int j = 0; j < 4; j++) acc[i][j] = 0ULL;

    float epsv = 0.f;
    if (MODE == 0) epsv = 1.0f + epsp[0];

    const float* A1 = (MODE == 0) ? g_h : g_t1;

    for (int k0 = 0; k0 < K; k0 += BK) {
        // ---- load A tile (fused elementwise) ----
        #pragma unroll
        for (int half = 0; half < 2; half++) {
            int r = ar + half * 64;
            int grow = brow + r;
            float4 v;
            if (grow < M) {
                size_t idx = (size_t)grow * K + k0 + ak;
                if (MODE == 0) {
                    float4 hv = *(const float4*)(A1 + idx);
                    float4 av = *(const float4*)(g_agg + idx);
                    v.x = fmaf(epsv, hv.x, av.x);
                    v.y = fmaf(epsv, hv.y, av.y);
                    v.z = fmaf(epsv, hv.z, av.z);
                    v.w = fmaf(epsv, hv.w, av.w);
                } else {
                    float4 tv = *(const float4*)(A1 + idx);
                    float4 ca = *(const float4*)(g_a + k0 + ak);
                    float4 cb = *(const float4*)(g_bc + k0 + ak);
                    v.x = fmaxf(fmaf(tv.x, ca.x, cb.x), 0.f);
                    v.y = fmaxf(fmaf(tv.y, ca.y, cb.y), 0.f);
                    v.z = fmaxf(fmaf(tv.z, ca.z, cb.z), 0.f);
                    v.w = fmaxf(fmaf(tv.w, ca.w, cb.w), 0.f);
                }
            } else {
                v = make_float4(0.f, 0.f, 0.f, 0.f);
            }
            As[ak + 0][r] = v.x;
            As[ak + 1][r] = v.y;
            As[ak + 2][r] = v.z;
            As[ak + 3][r] = v.w;
        }
        // ---- load B tile ----
        #pragma unroll
        for (int half = 0; half < 2; half++) {
            int r = br + half * 8;
            *(float4*)&Bs[r][bc] = *(const float4*)(B + (size_t)(k0 + r) * NC + bcol + bc);
        }
        __syncthreads();

        // ---- compute ----
        #pragma unroll
        for (int k = 0; k < BK; k++) {
            float4 a0 = *(const float4*)&As[k][ty * 4];
            float4 a1 = *(const float4*)&As[k][ty * 4 + 64];
            ulonglong2 b0 = *(const ulonglong2*)&Bs[k][tx * 4];
            ulonglong2 b1 = *(const ulonglong2*)&Bs[k][tx * 4 + 64];
            unsigned long long aa[8];
            aa[0] = bcast2(a0.x); aa[1] = bcast2(a0.y);
            aa[2] = bcast2(a0.z); aa[3] = bcast2(a0.w);
            aa[4] = bcast2(a1.x); aa[5] = bcast2(a1.y);
            aa[6] = bcast2(a1.z); aa[7] = bcast2(a1.w);
            #pragma unroll
            for (int i = 0; i < 8; i++) {
                acc[i][0] = ffma2(aa[i], b0.x, acc[i][0]);
                acc[i][1] = ffma2(aa[i], b0.y, acc[i][1]);
                acc[i][2] = ffma2(aa[i], b1.x, acc[i][2]);
                acc[i][3] = ffma2(aa[i], b1.y, acc[i][3]);
            }
        }
        __syncthreads();
    }

    // ---- store ----
    float* C = (MODE == 0) ? g_t1 : g_agg;
    #pragma unroll
    for (int i = 0; i < 8; i++) {
        int grow = brow + ty * 4 + ((i < 4) ? i : (i - 4 + 64));
        if (grow < M) {
            float* crow = C + (size_t)grow * NC + bcol;
            ulonglong2 u0; u0.x = acc[i][0]; u0.y = acc[i][1];
            *(float4*)(crow + tx * 4) = *(float4*)&u0;
            ulonglong2 u1; u1.x = acc[i][2]; u1.y = acc[i][3];
            *(float4*)(crow + tx * 4 + 64) = *(float4*)&u1;
        }
    }
}

// ---------------- column sum / sumsq reduction ----------------
// SRC 0: read g_t1 ; SRC 1: read g_agg
template <int SRC, int C>
__global__ void k_colreduce(int M) {
    const float* __restrict__ X = (SRC == 0) ? g_t1 : g_agg;
    int c = blockIdx.y * blockDim.x + threadIdx.x;
    float s = 0.f, q = 0.f;
    #pragma unroll 4
    for (int r = blockIdx.x; r < M; r += gridDim.x) {
        float v = X[(size_t)r * C + c];
        s += v;
        q = fmaf(v, v, q);
    }
    atomicAdd(&g_sum[c], s);
    atomicAdd(&g_sumsq[c], q);
}

// ---------------- BN finalize: a = g*rsqrt(var+1e-5), b = bt - mu*a ----------------
__global__ void k_bnfin(const float* __restrict__ g, const float* __restrict__ bt, float invM) {
    int c = blockIdx.x * blockDim.x + threadIdx.x;
    float mu = g_sum[c] * invM;
    float var = fmaf(-mu, mu, g_sumsq[c] * invM);
    float a = g[c] * rsqrtf(var + 1e-5f);
    g_a[c] = a;
    g_bc[c] = fmaf(-mu, a, bt[c]);
}

// ---------------- apply BN2 (+relu) to z2 (=g_agg), write h or d_out ----------------
template <int TO_OUT>
__global__ void k_apply(float* __restrict__ out, int relu) {
    int idx = blockIdx.x * blockDim.x + threadIdx.x;  // float4 index
    float4 v = ((const float4*)g_agg)[idx];
    int c = (idx * 4) & (DD - 1);
    float4 a = *(const float4*)(g_a + c);
    float4 b = *(const float4*)(g_bc + c);
    v.x = fmaf(v.x, a.x, b.x);
    v.y = fmaf(v.y, a.y, b.y);
    v.z = fmaf(v.z, a.z, b.z);
    v.w = fmaf(v.w, a.w, b.w);
    if (relu) {
        v.x = fmaxf(v.x, 0.f); v.y = fmaxf(v.y, 0.f);
        v.z = fmaxf(v.z, 0.f); v.w = fmaxf(v.w, 0.f);
    }
    if (TO_OUT) ((float4*)out)[idx] = v;
    else        ((float4*)g_h)[idx] = v;
}

// ---------------- launcher ----------------
extern "C" void kernel_launch(void* const* d_in, const int* in_sizes, int n_in,
                              void* d_out, int out_size) {
    const int*   x        = (const int*)d_in[0];
    const int*   ei       = (const int*)d_in[1];
    const float* attr     = (const float*)d_in[2];
    const float* node_emb = (const float*)d_in[4];
    const float* We       = (const float*)d_in[5];
    const float* be       = (const float*)d_in[6];
    const float* W1       = (const float*)d_in[7];
    const float* g1       = (const float*)d_in[9];
    const float* bt1      = (const float*)d_in[10];
    const float* W2       = (const float*)d_in[11];
    const float* eps      = (const float*)d_in[13];
    const float* gbn      = (const float*)d_in[14];
    const float* bbn      = (const float*)d_in[15];
    float* out = (float*)d_out;

    int M = in_sizes[0];          // N = 100000
    int E = in_sizes[1] / 2;      // 1600000
    float invM = 1.0f / (float)M;

    int ewGrid = (M * DD / 4 + 255) / 256;  // elementwise float4 grid (25000)
    dim3 gemm1_grid(HH / 128, (M + 127) / 128);
    dim3 gemm2_grid(DD / 128, (M + 127) / 128);

    k_init_h<<<M, 256>>>(x, node_emb);

    for (int l = 0; l < LL; l++) {
        // -- edge aggregation --
        k_zero_agg<<<ewGrid, 256>>>();
        k_edge<<<(E + EPB - 1) / EPB, 256>>>(ei, attr, We + (size_t)l * 7 * DD,
                                             be + (size_t)l * DD, E);

        // -- GEMM1: t1 = ((1+eps)h + agg) @ W1  (bias b1 cancels through BN) --
        k_gemm<0, DD, HH><<<gemm1_grid, 256>>>(W1 + (size_t)l * DD * HH, eps + l, M);

        // -- BN1 stats + finalize --
        k_zero_stats<<<2, 256>>>();
        {
            dim3 rg(1024, HH / 256);
            k_colreduce<0, HH><<<rg, 256>>>(M);
        }
        k_bnfin<<<HH / 256, 256>>>(g1 + (size_t)l * HH, bt1 + (size_t)l * HH, invM);

        // -- GEMM2: z2 = relu(BN1(t1)) @ W2  (bias b2 cancels through BN) --
        k_gemm<1, HH, DD><<<gemm2_grid, 256>>>(W2 + (size_t)l * HH * DD, eps + l, M);

        // -- BN2 stats + finalize --
        k_zero_stats<<<2, 256>>>();
        {
            dim3 rg(1024, DD / 256);
            k_colreduce<1, DD><<<rg, 256>>>(M);
        }
        k_bnfin<<<DD / 256, 256>>>(gbn + (size_t)l * DD, bbn + (size_t)l * DD, invM);

        // -- apply BN2 (+relu except last layer) --
        if (l == LL - 1) k_apply<1><<<ewGrid, 256>>>(out, 0);
        else             k_apply<0><<<ewGrid, 256>>>(out, 1);
    }
}

// round 2
// speedup vs baseline: 1.1175x; 1.1175x over previous
#include <cuda_runtime.h>
#include <math.h>

#define NN 100000
#define EE 1600000
#define DD 256
#define HH 512
#define LL 5
#define SCAN_B 512

// ---------------- device scratch (no allocs allowed) ----------------
__device__ float g_h[(size_t)NN * DD];     // node features
__device__ float g_agg[(size_t)NN * DD];   // aggregation buffer; reused as z2
__device__ float g_t1[(size_t)NN * HH];    // hidden activations
__device__ float g_sum[HH];
__device__ float g_sumsq[HH];
__device__ float g_a[HH];                  // BN scale
__device__ float g_bc[HH];                 // BN shift
// CSR build
__device__ int g_off[NN + 1];
__device__ int g_cursor[NN];
__device__ int g_eidx[EE];
__device__ int g_tmp[NN];
__device__ int g_bsum[SCAN_B];

// ---------------- f32x2 packed FMA helpers ----------------
__device__ __forceinline__ unsigned long long ffma2(unsigned long long a,
                                                    unsigned long long b,
                                                    unsigned long long c) {
    unsigned long long d;
    asm("fma.rn.f32x2 %0, %1, %2, %3;" : "=l"(d) : "l"(a), "l"(b), "l"(c));
    return d;
}
__device__ __forceinline__ unsigned long long bcast2(float x) {
    unsigned long long r;
    asm("mov.b64 %0, {%1, %1};" : "=l"(r) : "f"(x));
    return r;
}

// ---------------- init: h = node_emb[x] ----------------
__global__ void k_init_h(const int* __restrict__ x, const float* __restrict__ emb) {
    int i = blockIdx.x;
    int d = threadIdx.x;
    g_h[(size_t)i * DD + d] = emb[(size_t)x[i] * DD + d];
}

// ---------------- CSR build ----------------
__global__ void k_zero_cursor(int M) {
    int i = blockIdx.x * blockDim.x + threadIdx.x;
    if (i < M) g_cursor[i] = 0;
}
__global__ void k_hist(const int* __restrict__ dst, int E) {
    int e = blockIdx.x * blockDim.x + threadIdx.x;
    if (e < E) atomicAdd(&g_cursor[dst[e]], 1);
}
__global__ void k_scan1(int M) {  // 512 threads/block; inclusive scan per block
    __shared__ int s[SCAN_B];
    int t = threadIdx.x;
    int i = blockIdx.x * SCAN_B + t;
    int v = (i < M) ? g_cursor[i] : 0;
    s[t] = v;
    __syncthreads();
    for (int d = 1; d < SCAN_B; d <<= 1) {
        int x = (t >= d) ? s[t - d] : 0;
        __syncthreads();
        s[t] += x;
        __syncthreads();
    }
    if (i < M) g_tmp[i] = s[t];
    if (t == SCAN_B - 1) g_bsum[blockIdx.x] = s[t];
}
__global__ void k_scan2(int NB) {  // 1 block, 512 threads; exclusive scan of block sums
    __shared__ int s[SCAN_B];
    int t = threadIdx.x;
    int v = (t < NB) ? g_bsum[t] : 0;
    s[t] = v;
    __syncthreads();
    for (int d = 1; d < SCAN_B; d <<= 1) {
        int x = (t >= d) ? s[t - d] : 0;
        __syncthreads();
        s[t] += x;
        __syncthreads();
    }
    if (t < NB) g_bsum[t] = s[t] - v;  // exclusive
}
__global__ void k_scan3(int M) {
    int i = blockIdx.x * SCAN_B + threadIdx.x;
    if (i < M) g_off[i + 1] = g_tmp[i] + g_bsum[blockIdx.x];
    if (i == 0) g_off[0] = 0;
}
__global__ void k_setcur(int M) {
    int i = blockIdx.x * blockDim.x + threadIdx.x;
    if (i < M) g_cursor[i] = g_off[i];
}
__global__ void k_scatter(const int* __restrict__ dst, int E) {
    int e = blockIdx.x * blockDim.x + threadIdx.x;
    if (e < E) {
        int p = atomicAdd(&g_cursor[dst[e]], 1);
        g_eidx[p] = e;
    }
}

// ---------------- gather: agg[n] = sum_{e: dst=n} relu(h[src] + attr@We + be) ----------------
__global__ void __launch_bounds__(256)
k_gather(const int* __restrict__ src, const float* __restrict__ attr,
         const float* __restrict__ We, const float* __restrict__ be, int M) {
    int t = threadIdx.x;
    int cg = (t & 63) * 4;              // column group (4 floats)
    int n = blockIdx.x * 4 + (t >> 6);  // node

    // register-resident We columns + bias
    float4 w[7];
    #pragma unroll
    for (int k = 0; k < 7; k++) w[k] = *(const float4*)(We + k * DD + cg);
    float4 bev = *(const float4*)(be + cg);

    if (n >= M) return;
    int p0 = g_off[n], p1 = g_off[n + 1];
    float4 acc = make_float4(0.f, 0.f, 0.f, 0.f);
    #pragma unroll 2
    for (int p = p0; p < p1; p++) {
        int e = g_eidx[p];
        int s = __ldg(src + e);
        const float* at = attr + (size_t)e * 7;
        float4 emb = bev;
        #pragma unroll
        for (int k = 0; k < 7; k++) {
            float a = __ldg(at + k);
            emb.x = fmaf(a, w[k].x, emb.x);
            emb.y = fmaf(a, w[k].y, emb.y);
            emb.z = fmaf(a, w[k].z, emb.z);
            emb.w = fmaf(a, w[k].w, emb.w);
        }
        float4 hv = *(const float4*)(g_h + (size_t)s * DD + cg);
        acc.x += fmaxf(hv.x + emb.x, 0.f);
        acc.y += fmaxf(hv.y + emb.y, 0.f);
        acc.z += fmaxf(hv.z + emb.z, 0.f);
        acc.w += fmaxf(hv.w + emb.w, 0.f);
    }
    *(float4*)(g_agg + (size_t)n * DD + cg) = acc;
}

// ---------------- zero BN stats ----------------
__global__ void k_zero_stats() {
    int i = blockIdx.x * blockDim.x + threadIdx.x;
    if (i < HH) { g_sum[i] = 0.f; g_sumsq[i] = 0.f; }
}

// ---------------- GEMM: C = f(A) @ B, double-buffered, fused BN stats ----------------
// MODE 0: A[i,k] = (1+eps)*h[i,k] + agg[i,k];  C -> g_t1   (K=DD, NC=HH)
// MODE 1: A[i,k] = relu(t1[i,k]*g_a[k]+g_bc[k]); C -> g_agg (K=HH, NC=DD)
template <int MODE, int K, int NC>
__global__ void __launch_bounds__(256, 2)
k_gemm(const float* __restrict__ B, const float* __restrict__ epsp, int M) {
    const int BM = 128, BN = 128, BK = 16;
    __shared__ float As[2][BK][BM + 4];
    __shared__ float Bs[2][BK][BN];
    __shared__ float s_sum[BN], s_sq[BN];

    int tid = threadIdx.x;
    int tx = tid % 16, ty = tid / 16;
    int brow = blockIdx.y * BM, bcol = blockIdx.x * BN;

    int ar = tid / 4, ak = (tid % 4) * 4;   // A-loader
    int br = tid / 32, bc = (tid % 32) * 4; // B-loader

    float epsv = (MODE == 0) ? (1.0f + epsp[0]) : 0.f;
    const float* A1 = (MODE == 0) ? g_h : g_t1;

    unsigned long long acc[8][4];
    #pragma unroll
    for (int i = 0; i < 8; i++)
        #pragma unroll
        for (int j = 0; j < 4; j++) acc[i][j] = 0ULL;

    auto ldA = [&](int k0, int half) -> float4 {
        int grow = brow + ar + half * 64;
        float4 v = make_float4(0.f, 0.f, 0.f, 0.f);
        if (grow < M) {
            size_t idx = (size_t)grow * K + k0 + ak;
            if (MODE == 0) {
                float4 hv = *(const float4*)(A1 + idx);
                float4 av = *(const float4*)(g_agg + idx);
                v.x = fmaf(epsv, hv.x, av.x);
                v.y = fmaf(epsv, hv.y, av.y);
                v.z = fmaf(epsv, hv.z, av.z);
                v.w = fmaf(epsv, hv.w, av.w);
            } else {
                float4 tv = *(const float4*)(A1 + idx);
                float4 ca = *(const float4*)(g_a + k0 + ak);
                float4 cb = *(const float4*)(g_bc + k0 + ak);
                v.x = fmaxf(fmaf(tv.x, ca.x, cb.x), 0.f);
                v.y = fmaxf(fmaf(tv.y, ca.y, cb.y), 0.f);
                v.z = fmaxf(fmaf(tv.z, ca.z, cb.z), 0.f);
                v.w = fmaxf(fmaf(tv.w, ca.w, cb.w), 0.f);
            }
        }
        return v;
    };

    // prologue: prefetch tile 0
    float4 ra0 = ldA(0, 0), ra1 = ldA(0, 1);
    float4 rb0 = *(const float4*)(B + (size_t)br * NC + bcol + bc);
    float4 rb1 = *(const float4*)(B + (size_t)(br + 8) * NC + bcol + bc);

    int buf = 0;
    for (int k0 = 0; k0 < K; k0 += BK, buf ^= 1) {
        // store prefetched regs to SMEM
        As[buf][ak + 0][ar] = ra0.x;
        As[buf][ak + 1][ar] = ra0.y;
        As[buf][ak + 2][ar] = ra0.z;
        As[buf][ak + 3][ar] = ra0.w;
        As[buf][ak + 0][ar + 64] = ra1.x;
        As[buf][ak + 1][ar + 64] = ra1.y;
        As[buf][ak + 2][ar + 64] = ra1.z;
        As[buf][ak + 3][ar + 64] = ra1.w;
        *(float4*)&Bs[buf][br][bc] = rb0;
        *(float4*)&Bs[buf][br + 8][bc] = rb1;
        __syncthreads();

        int kn = k0 + BK;
        if (kn < K) {  // prefetch next tile
            ra0 = ldA(kn, 0);
            ra1 = ldA(kn, 1);
            rb0 = *(const float4*)(B + (size_t)(kn + br) * NC + bcol + bc);
            rb1 = *(const float4*)(B + (size_t)(kn + br + 8) * NC + bcol + bc);
        }

        #pragma unroll
        for (int k = 0; k < BK; k++) {
            float4 a0 = *(const float4*)&As[buf][k][ty * 4];
            float4 a1 = *(const float4*)&As[buf][k][ty * 4 + 64];
            ulonglong2 b0 = *(const ulonglong2*)&Bs[buf][k][tx * 4];
            ulonglong2 b1 = *(const ulonglong2*)&Bs[buf][k][tx * 4 + 64];
            unsigned long long aa[8];
            aa[0] = bcast2(a0.x); aa[1] = bcast2(a0.y);
            aa[2] = bcast2(a0.z); aa[3] = bcast2(a0.w);
            aa[4] = bcast2(a1.x); aa[5] = bcast2(a1.y);
            aa[6] = bcast2(a1.z); aa[7] = bcast2(a1.w);
            #pragma unroll
            for (int i = 0; i < 8; i++) {
                acc[i][0] = ffma2(aa[i], b0.x, acc[i][0]);
                acc[i][1] = ffma2(aa[i], b0.y, acc[i][1]);
                acc[i][2] = ffma2(aa[i], b1.x, acc[i][2]);
                acc[i][3] = ffma2(aa[i], b1.y, acc[i][3]);
            }
        }
        __syncthreads();
    }

    // ---- epilogue: store C + fused BN column stats ----
    if (tid < BN) { s_sum[tid] = 0.f; s_sq[tid] = 0.f; }
    __syncthreads();

    float* C = (MODE == 0) ? g_t1 : g_agg;
    float csum[8], csq[8];
    #pragma unroll
    for (int j = 0; j < 8; j++) { csum[j] = 0.f; csq[j] = 0.f; }

    #pragma unroll
    for (int i = 0; i < 8; i++) {
        int grow = brow + ty * 4 + ((i < 4) ? i : (i - 4 + 64));
        if (grow < M) {
            float* crow = C + (size_t)grow * NC + bcol;
            ulonglong2 u0; u0.x = acc[i][0]; u0.y = acc[i][1];
            ulonglong2 u1; u1.x = acc[i][2]; u1.y = acc[i][3];
            *(float4*)(crow + tx * 4) = *(float4*)&u0;
            *(float4*)(crow + tx * 4 + 64) = *(float4*)&u1;
            const float* f0 = (const float*)&u0;
            const float* f1 = (const float*)&u1;
            #pragma unroll
            for (int j = 0; j < 4; j++) {
                csum[j] += f0[j];     csq[j] = fmaf(f0[j], f0[j], csq[j]);
                csum[4 + j] += f1[j]; csq[4 + j] = fmaf(f1[j], f1[j], csq[4 + j]);
            }
        }
    }
    #pragma unroll
    for (int j = 0; j < 4; j++) {
        atomicAdd(&s_sum[tx * 4 + j], csum[j]);
        atomicAdd(&s_sq[tx * 4 + j], csq[j]);
        atomicAdd(&s_sum[64 + tx * 4 + j], csum[4 + j]);
        atomicAdd(&s_sq[64 + tx * 4 + j], csq[4 + j]);
    }
    __syncthreads();
    if (tid < BN) {
        atomicAdd(&g_sum[bcol + tid], s_sum[tid]);
        atomicAdd(&g_sumsq[bcol + tid], s_sq[tid]);
    }
}

// ---------------- BN finalize: a = g*rsqrt(var+1e-5), b = bt - mu*a ----------------
__global__ void k_bnfin(const float* __restrict__ g, const float* __restrict__ bt, float invM) {
    int c = blockIdx.x * blockDim.x + threadIdx.x;
    float mu = g_sum[c] * invM;
    float var = fmaf(-mu, mu, g_sumsq[c] * invM);
    float a = g[c] * rsqrtf(var + 1e-5f);
    g_a[c] = a;
    g_bc[c] = fmaf(-mu, a, bt[c]);
}

// ---------------- apply BN2 (+relu) to z2 (=g_agg), write h or d_out ----------------
template <int TO_OUT>
__global__ void k_apply(float* __restrict__ out, int relu) {
    int idx = blockIdx.x * blockDim.x + threadIdx.x;  // float4 index
    float4 v = ((const float4*)g_agg)[idx];
    int c = (idx * 4) & (DD - 1);
    float4 a = *(const float4*)(g_a + c);
    float4 b = *(const float4*)(g_bc + c);
    v.x = fmaf(v.x, a.x, b.x);
    v.y = fmaf(v.y, a.y, b.y);
    v.z = fmaf(v.z, a.z, b.z);
    v.w = fmaf(v.w, a.w, b.w);
    if (relu) {
        v.x = fmaxf(v.x, 0.f); v.y = fmaxf(v.y, 0.f);
        v.z = fmaxf(v.z, 0.f); v.w = fmaxf(v.w, 0.f);
    }
    if (TO_OUT) ((float4*)out)[idx] = v;
    else        ((float4*)g_h)[idx] = v;
}

// ---------------- launcher ----------------
extern "C" void kernel_launch(void* const* d_in, const int* in_sizes, int n_in,
                              void* d_out, int out_size) {
    const int*   x        = (const int*)d_in[0];
    const int*   ei       = (const int*)d_in[1];
    const float* attr     = (const float*)d_in[2];
    const float* node_emb = (const float*)d_in[4];
    const float* We       = (const float*)d_in[5];
    const float* be       = (const float*)d_in[6];
    const float* W1       = (const float*)d_in[7];
    const float* g1       = (const float*)d_in[9];
    const float* bt1      = (const float*)d_in[10];
    const float* W2       = (const float*)d_in[11];
    const float* eps      = (const float*)d_in[13];
    const float* gbn      = (const float*)d_in[14];
    const float* bbn      = (const float*)d_in[15];
    float* out = (float*)d_out;

    int M = in_sizes[0];          // N = 100000
    int E = in_sizes[1] / 2;      // 1600000
    const int* dst = ei + E;
    float invM = 1.0f / (float)M;

    int ewGrid = (M * DD / 4 + 255) / 256;
    dim3 gemm1_grid(HH / 128, (M + 127) / 128);
    dim3 gemm2_grid(DD / 128, (M + 127) / 128);
    int nb = (M + SCAN_B - 1) / SCAN_B;

    // ---- CSR build (once per call) ----
    k_zero_cursor<<<(M + 255) / 256, 256>>>(M);
    k_hist<<<(E + 255) / 256, 256>>>(dst, E);
    k_scan1<<<nb, SCAN_B>>>(M);
    k_scan2<<<1, SCAN_B>>>(nb);
    k_scan3<<<nb, SCAN_B>>>(M);
    k_setcur<<<(M + 255) / 256, 256>>>(M);
    k_scatter<<<(E + 255) / 256, 256>>>(dst, E);

    k_init_h<<<M, 256>>>(x, node_emb);

    for (int l = 0; l < LL; l++) {
        // -- edge aggregation (gather, no atomics) --
        k_gather<<<(M + 3) / 4, 256>>>(ei, attr, We + (size_t)l * 7 * DD,
                                       be + (size_t)l * DD, M);

        // -- GEMM1 (+ fused BN1 stats) --
        k_zero_stats<<<2, 256>>>();
        k_gemm<0, DD, HH><<<gemm1_grid, 256>>>(W1 + (size_t)l * DD * HH, eps + l, M);
        k_bnfin<<<HH / 256, 256>>>(g1 + (size_t)l * HH, bt1 + (size_t)l * HH, invM);

        // -- GEMM2 (+ fused BN2 stats) --
        k_zero_stats<<<2, 256>>>();
        k_gemm<1, HH, DD><<<gemm2_grid, 256>>>(W2 + (size_t)l * HH * DD, eps + l, M);
        k_bnfin<<<DD / 256, 256>>>(gbn + (size_t)l * DD, bbn + (size_t)l * DD, invM);

        // -- apply BN2 (+relu except last layer) --
        if (l == LL - 1) k_apply<1><<<ewGrid, 256>>>(out, 0);
        else             k_apply<0><<<ewGrid, 256>>>(out, 1);
    }
}

// round 3
// speedup vs baseline: 1.2286x; 1.0994x over previous
#include <cuda_runtime.h>
#include <math.h>

#define NN 100000
#define EE 1600000
#define DD 256
#define HH 512
#define LL 5
#define SCAN_B 512

// ---------------- device scratch (no allocs allowed) ----------------
__device__ float g_h[(size_t)NN * DD];     // node features
__device__ float g_agg[(size_t)NN * DD];   // aggregation buffer; reused as z2
__device__ float g_t1[(size_t)NN * HH];    // hidden activations
__device__ float g_sum[HH];
__device__ float g_sumsq[HH];
__device__ float g_a[HH];                  // BN scale
__device__ float g_bc[HH];                 // BN shift
// CSR build + permuted edge data
__device__ int g_off[NN + 1];
__device__ int g_cursor[NN];
__device__ int g_tmp[NN];
__device__ int g_bsum[SCAN_B];
__device__ int g_srcp[EE];                 // src node id in CSR order
__device__ float g_attr8[(size_t)EE * 8];  // edge attrs (7 + pad) in CSR order

// ---------------- f32x2 packed FMA helpers ----------------
__device__ __forceinline__ unsigned long long ffma2(unsigned long long a,
                                                    unsigned long long b,
                                                    unsigned long long c) {
    unsigned long long d;
    asm("fma.rn.f32x2 %0, %1, %2, %3;" : "=l"(d) : "l"(a), "l"(b), "l"(c));
    return d;
}
__device__ __forceinline__ unsigned long long bcast2(float x) {
    unsigned long long r;
    asm("mov.b64 %0, {%1, %1};" : "=l"(r) : "f"(x));
    return r;
}

// ---------------- init: h = node_emb[x] ----------------
__global__ void k_init_h(const int* __restrict__ x, const float* __restrict__ emb) {
    int i = blockIdx.x;
    int d = threadIdx.x;
    g_h[(size_t)i * DD + d] = emb[(size_t)x[i] * DD + d];
}

// ---------------- CSR build ----------------
__global__ void k_zero_cursor(int M) {
    int i = blockIdx.x * blockDim.x + threadIdx.x;
    if (i < M) g_cursor[i] = 0;
}
__global__ void k_hist(const int* __restrict__ dst, int E) {
    int e = blockIdx.x * blockDim.x + threadIdx.x;
    if (e < E) atomicAdd(&g_cursor[dst[e]], 1);
}
__global__ void k_scan1(int M) {
    __shared__ int s[SCAN_B];
    int t = threadIdx.x;
    int i = blockIdx.x * SCAN_B + t;
    int v = (i < M) ? g_cursor[i] : 0;
    s[t] = v;
    __syncthreads();
    for (int d = 1; d < SCAN_B; d <<= 1) {
        int x = (t >= d) ? s[t - d] : 0;
        __syncthreads();
        s[t] += x;
        __syncthreads();
    }
    if (i < M) g_tmp[i] = s[t];
    if (t == SCAN_B - 1) g_bsum[blockIdx.x] = s[t];
}
__global__ void k_scan2(int NB) {
    __shared__ int s[SCAN_B];
    int t = threadIdx.x;
    int v = (t < NB) ? g_bsum[t] : 0;
    s[t] = v;
    __syncthreads();
    for (int d = 1; d < SCAN_B; d <<= 1) {
        int x = (t >= d) ? s[t - d] : 0;
        __syncthreads();
        s[t] += x;
        __syncthreads();
    }
    if (t < NB) g_bsum[t] = s[t] - v;  // exclusive
}
__global__ void k_scan3(int M) {
    int i = blockIdx.x * SCAN_B + threadIdx.x;
    if (i < M) g_off[i + 1] = g_tmp[i] + g_bsum[blockIdx.x];
    if (i == 0) g_off[0] = 0;
}
__global__ void k_setcur(int M) {
    int i = blockIdx.x * blockDim.x + threadIdx.x;
    if (i < M) g_cursor[i] = g_off[i];
}
// scatter edges into CSR order, materializing src_perm and padded attr
__global__ void k_scatter(const int* __restrict__ src, const int* __restrict__ dst,
                          const float* __restrict__ attr, int E) {
    int e = blockIdx.x * blockDim.x + threadIdx.x;
    if (e < E) {
        int p = atomicAdd(&g_cursor[dst[e]], 1);
        g_srcp[p] = src[e];
        const float* at = attr + (size_t)e * 7;
        float* o = g_attr8 + (size_t)p * 8;
        float4 v0 = make_float4(at[0], at[1], at[2], at[3]);
        float4 v1 = make_float4(at[4], at[5], at[6], 0.f);
        *(float4*)(o) = v0;
        *(float4*)(o + 4) = v1;
    }
}

// ---------------- gather: agg[n] = sum_{e in CSR[n]} relu(h[src] + attr@We + be) ----
__global__ void __launch_bounds__(256)
k_gather(const float* __restrict__ We, const float* __restrict__ be, int M) {
    int t = threadIdx.x;
    int cg = (t & 63) * 4;              // 4-column group
    int n = blockIdx.x * 4 + (t >> 6);  // node

    float4 w[7];
    #pragma unroll
    for (int k = 0; k < 7; k++) w[k] = *(const float4*)(We + k * DD + cg);
    float4 bev = *(const float4*)(be + cg);

    if (n >= M) return;
    int p0 = g_off[n], p1 = g_off[n + 1];
    float4 acc = make_float4(0.f, 0.f, 0.f, 0.f);
    #pragma unroll 4
    for (int p = p0; p < p1; p++) {
        int s = g_srcp[p];
        float4 a0 = *(const float4*)(g_attr8 + (size_t)p * 8);
        float4 a1 = *(const float4*)(g_attr8 + (size_t)p * 8 + 4);
        float4 hv = *(const float4*)(g_h + (size_t)s * DD + cg);
        float4 emb = bev;
        emb.x = fmaf(a0.x, w[0].x, emb.x); emb.y = fmaf(a0.x, w[0].y, emb.y);
        emb.z = fmaf(a0.x, w[0].z, emb.z); emb.w = fmaf(a0.x, w[0].w, emb.w);
        emb.x = fmaf(a0.y, w[1].x, emb.x); emb.y = fmaf(a0.y, w[1].y, emb.y);
        emb.z = fmaf(a0.y, w[1].z, emb.z); emb.w = fmaf(a0.y, w[1].w, emb.w);
        emb.x = fmaf(a0.z, w[2].x, emb.x); emb.y = fmaf(a0.z, w[2].y, emb.y);
        emb.z = fmaf(a0.z, w[2].z, emb.z); emb.w = fmaf(a0.z, w[2].w, emb.w);
        emb.x = fmaf(a0.w, w[3].x, emb.x); emb.y = fmaf(a0.w, w[3].y, emb.y);
        emb.z = fmaf(a0.w, w[3].z, emb.z); emb.w = fmaf(a0.w, w[3].w, emb.w);
        emb.x = fmaf(a1.x, w[4].x, emb.x); emb.y = fmaf(a1.x, w[4].y, emb.y);
        emb.z = fmaf(a1.x, w[4].z, emb.z); emb.w = fmaf(a1.x, w[4].w, emb.w);
        emb.x = fmaf(a1.y, w[5].x, emb.x); emb.y = fmaf(a1.y, w[5].y, emb.y);
        emb.z = fmaf(a1.y, w[5].z, emb.z); emb.w = fmaf(a1.y, w[5].w, emb.w);
        emb.x = fmaf(a1.z, w[6].x, emb.x); emb.y = fmaf(a1.z, w[6].y, emb.y);
        emb.z = fmaf(a1.z, w[6].z, emb.z); emb.w = fmaf(a1.z, w[6].w, emb.w);
        acc.x += fmaxf(hv.x + emb.x, 0.f);
        acc.y += fmaxf(hv.y + emb.y, 0.f);
        acc.z += fmaxf(hv.z + emb.z, 0.f);
        acc.w += fmaxf(hv.w + emb.w, 0.f);
    }
    *(float4*)(g_agg + (size_t)n * DD + cg) = acc;
}

// ---------------- zero BN stats ----------------
__global__ void k_zero_stats() {
    int i = blockIdx.x * blockDim.x + threadIdx.x;
    if (i < HH) { g_sum[i] = 0.f; g_sumsq[i] = 0.f; }
}

// ---------------- GEMM: C = f(A) @ B, double-buffered, fused BN stats ----------------
template <int MODE, int K, int NC>
__global__ void __launch_bounds__(256, 2)
k_gemm(const float* __restrict__ B, const float* __restrict__ epsp, int M) {
    const int BM = 128, BN = 128, BK = 16;
    __shared__ float As[2][BK][BM + 4];
    __shared__ float Bs[2][BK][BN];
    __shared__ float s_sum[BN], s_sq[BN];

    int tid = threadIdx.x;
    int tx = tid % 16, ty = tid / 16;
    int brow = blockIdx.y * BM, bcol = blockIdx.x * BN;

    int ar = tid / 4, ak = (tid % 4) * 4;
    int br = tid / 32, bc = (tid % 32) * 4;

    float epsv = (MODE == 0) ? (1.0f + epsp[0]) : 0.f;
    const float* A1 = (MODE == 0) ? g_h : g_t1;

    unsigned long long acc[8][4];
    #pragma unroll
    for (int i = 0; i < 8; i++)
        #pragma unroll
        for (int j = 0; j < 4; j++) acc[i][j] = 0ULL;

    auto ldA = [&](int k0, int half) -> float4 {
        int grow = brow + ar + half * 64;
        float4 v = make_float4(0.f, 0.f, 0.f, 0.f);
        if (grow < M) {
            size_t idx = (size_t)grow * K + k0 + ak;
            if (MODE == 0) {
                float4 hv = *(const float4*)(A1 + idx);
                float4 av = *(const float4*)(g_agg + idx);
                v.x = fmaf(epsv, hv.x, av.x);
                v.y = fmaf(epsv, hv.y, av.y);
                v.z = fmaf(epsv, hv.z, av.z);
                v.w = fmaf(epsv, hv.w, av.w);
            } else {
                float4 tv = *(const float4*)(A1 + idx);
                float4 ca = *(const float4*)(g_a + k0 + ak);
                float4 cb = *(const float4*)(g_bc + k0 + ak);
                v.x = fmaxf(fmaf(tv.x, ca.x, cb.x), 0.f);
                v.y = fmaxf(fmaf(tv.y, ca.y, cb.y), 0.f);
                v.z = fmaxf(fmaf(tv.z, ca.z, cb.z), 0.f);
                v.w = fmaxf(fmaf(tv.w, ca.w, cb.w), 0.f);
            }
        }
        return v;
    };

    float4 ra0 = ldA(0, 0), ra1 = ldA(0, 1);
    float4 rb0 = *(const float4*)(B + (size_t)br * NC + bcol + bc);
    float4 rb1 = *(const float4*)(B + (size_t)(br + 8) * NC + bcol + bc);

    int buf = 0;
    for (int k0 = 0; k0 < K; k0 += BK, buf ^= 1) {
        As[buf][ak + 0][ar] = ra0.x;
        As[buf][ak + 1][ar] = ra0.y;
        As[buf][ak + 2][ar] = ra0.z;
        As[buf][ak + 3][ar] = ra0.w;
        As[buf][ak + 0][ar + 64] = ra1.x;
        As[buf][ak + 1][ar + 64] = ra1.y;
        As[buf][ak + 2][ar + 64] = ra1.z;
        As[buf][ak + 3][ar + 64] = ra1.w;
        *(float4*)&Bs[buf][br][bc] = rb0;
        *(float4*)&Bs[buf][br + 8][bc] = rb1;
        __syncthreads();

        int kn = k0 + BK;
        if (kn < K) {
            ra0 = ldA(kn, 0);
            ra1 = ldA(kn, 1);
            rb0 = *(const float4*)(B + (size_t)(kn + br) * NC + bcol + bc);
            rb1 = *(const float4*)(B + (size_t)(kn + br + 8) * NC + bcol + bc);
        }

        #pragma unroll
        for (int k = 0; k < BK; k++) {
            float4 a0 = *(const float4*)&As[buf][k][ty * 4];
            float4 a1 = *(const float4*)&As[buf][k][ty * 4 + 64];
            ulonglong2 b0 = *(const ulonglong2*)&Bs[buf][k][tx * 4];
            ulonglong2 b1 = *(const ulonglong2*)&Bs[buf][k][tx * 4 + 64];
            unsigned long long aa[8];
            aa[0] = bcast2(a0.x); aa[1] = bcast2(a0.y);
            aa[2] = bcast2(a0.z); aa[3] = bcast2(a0.w);
            aa[4] = bcast2(a1.x); aa[5] = bcast2(a1.y);
            aa[6] = bcast2(a1.z); aa[7] = bcast2(a1.w);
            #pragma unroll
            for (int i = 0; i < 8; i++) {
                acc[i][0] = ffma2(aa[i], b0.x, acc[i][0]);
                acc[i][1] = ffma2(aa[i], b0.y, acc[i][1]);
                acc[i][2] = ffma2(aa[i], b1.x, acc[i][2]);
                acc[i][3] = ffma2(aa[i], b1.y, acc[i][3]);
            }
        }
        __syncthreads();
    }

    // ---- epilogue: store C + fused BN column stats ----
    if (tid < BN) { s_sum[tid] = 0.f; s_sq[tid] = 0.f; }
    __syncthreads();

    float* C = (MODE == 0) ? g_t1 : g_agg;
    float csum[8], csq[8];
    #pragma unroll
    for (int j = 0; j < 8; j++) { csum[j] = 0.f; csq[j] = 0.f; }

    #pragma unroll
    for (int i = 0; i < 8; i++) {
        int grow = brow + ty * 4 + ((i < 4) ? i : (i - 4 + 64));
        if (grow < M) {
            float* crow = C + (size_t)grow * NC + bcol;
            ulonglong2 u0; u0.x = acc[i][0]; u0.y = acc[i][1];
            ulonglong2 u1; u1.x = acc[i][2]; u1.y = acc[i][3];
            *(float4*)(crow + tx * 4) = *(float4*)&u0;
            *(float4*)(crow + tx * 4 + 64) = *(float4*)&u1;
            const float* f0 = (const float*)&u0;
            const float* f1 = (const float*)&u1;
            #pragma unroll
            for (int j = 0; j < 4; j++) {
                csum[j] += f0[j];     csq[j] = fmaf(f0[j], f0[j], csq[j]);
                csum[4 + j] += f1[j]; csq[4 + j] = fmaf(f1[j], f1[j], csq[4 + j]);
            }
        }
    }
    #pragma unroll
    for (int j = 0; j < 4; j++) {
        atomicAdd(&s_sum[tx * 4 + j], csum[j]);
        atomicAdd(&s_sq[tx * 4 + j], csq[j]);
        atomicAdd(&s_sum[64 + tx * 4 + j], csum[4 + j]);
        atomicAdd(&s_sq[64 + tx * 4 + j], csq[4 + j]);
    }
    __syncthreads();
    if (tid < BN) {
        atomicAdd(&g_sum[bcol + tid], s_sum[tid]);
        atomicAdd(&g_sumsq[bcol + tid], s_sq[tid]);
    }
}

// ---------------- BN finalize ----------------
__global__ void k_bnfin(const float* __restrict__ g, const float* __restrict__ bt, float invM) {
    int c = blockIdx.x * blockDim.x + threadIdx.x;
    float mu = g_sum[c] * invM;
    float var = fmaf(-mu, mu, g_sumsq[c] * invM);
    float a = g[c] * rsqrtf(var + 1e-5f);
    g_a[c] = a;
    g_bc[c] = fmaf(-mu, a, bt[c]);
}

// ---------------- apply BN2 (+relu) to z2 (=g_agg), write h or d_out ----------------
template <int TO_OUT>
__global__ void k_apply(float* __restrict__ out, int relu) {
    int idx = blockIdx.x * blockDim.x + threadIdx.x;
    float4 v = ((const float4*)g_agg)[idx];
    int c = (idx * 4) & (DD - 1);
    float4 a = *(const float4*)(g_a + c);
    float4 b = *(const float4*)(g_bc + c);
    v.x = fmaf(v.x, a.x, b.x);
    v.y = fmaf(v.y, a.y, b.y);
    v.z = fmaf(v.z, a.z, b.z);
    v.w = fmaf(v.w, a.w, b.w);
    if (relu) {
        v.x = fmaxf(v.x, 0.f); v.y = fmaxf(v.y, 0.f);
        v.z = fmaxf(v.z, 0.f); v.w = fmaxf(v.w, 0.f);
    }
    if (TO_OUT) ((float4*)out)[idx] = v;
    else        ((float4*)g_h)[idx] = v;
}

// ---------------- launcher ----------------
extern "C" void kernel_launch(void* const* d_in, const int* in_sizes, int n_in,
                              void* d_out, int out_size) {
    const int*   x        = (const int*)d_in[0];
    const int*   ei       = (const int*)d_in[1];
    const float* attr     = (const float*)d_in[2];
    const float* node_emb = (const float*)d_in[4];
    const float* We       = (const float*)d_in[5];
    const float* be       = (const float*)d_in[6];
    const float* W1       = (const float*)d_in[7];
    const float* g1       = (const float*)d_in[9];
    const float* bt1      = (const float*)d_in[10];
    const float* W2       = (const float*)d_in[11];
    const float* eps      = (const float*)d_in[13];
    const float* gbn      = (const float*)d_in[14];
    const float* bbn      = (const float*)d_in[15];
    float* out = (float*)d_out;

    int M = in_sizes[0];
    int E = in_sizes[1] / 2;
    const int* dst = ei + E;
    float invM = 1.0f / (float)M;

    int ewGrid = (M * DD / 4 + 255) / 256;
    dim3 gemm1_grid(HH / 128, (M + 127) / 128);
    dim3 gemm2_grid(DD / 128, (M + 127) / 128);
    int nb = (M + SCAN_B - 1) / SCAN_B;

    // ---- CSR build + edge-data permute (once per call) ----
    k_zero_cursor<<<(M + 255) / 256, 256>>>(M);
    k_hist<<<(E + 255) / 256, 256>>>(dst, E);
    k_scan1<<<nb, SCAN_B>>>(M);
    k_scan2<<<1, SCAN_B>>>(nb);
    k_scan3<<<nb, SCAN_B>>>(M);
    k_setcur<<<(M + 255) / 256, 256>>>(M);
    k_scatter<<<(E + 255) / 256, 256>>>(ei, dst, attr, E);

    k_init_h<<<M, 256>>>(x, node_emb);

    for (int l = 0; l < LL; l++) {
        k_gather<<<(M + 3) / 4, 256>>>(We + (size_t)l * 7 * DD, be + (size_t)l * DD, M);

        k_zero_stats<<<2, 256>>>();
        k_gemm<0, DD, HH><<<gemm1_grid, 256>>>(W1 + (size_t)l * DD * HH, eps + l, M);
        k_bnfin<<<HH / 256, 256>>>(g1 + (size_t)l * HH, bt1 + (size_t)l * HH, invM);

        k_zero_stats<<<2, 256>>>();
        k_gemm<1, HH, DD><<<gemm2_grid, 256>>>(W2 + (size_t)l * HH * DD, eps + l, M);
        k_bnfin<<<DD / 256, 256>>>(gbn + (size_t)l * DD, bbn + (size_t)l * DD, invM);

        if (l == LL - 1) k_apply<1><<<ewGrid, 256>>>(out, 0);
        else             k_apply<0><<<ewGrid, 256>>>(out, 1);
    }
}

// round 6
// speedup vs baseline: 1.3137x; 1.0692x over previous
#include <cuda_runtime.h>
#include <cuda_bf16.h>
#include <math.h>
#include <stdint.h>

#define NN 100000
#define EE 1600000
#define DD 256
#define HH 512
#define LL 5
#define SCAN_B 512

// ---------------- device scratch (no allocs allowed) ----------------
__device__ float g_h[(size_t)NN * DD];
__device__ float g_agg[(size_t)NN * DD];       // agg; reused as z2
__device__ float g_t1[(size_t)NN * HH];
__device__ float g_sum[HH];
__device__ float g_sumsq[HH];
__device__ float g_a[HH];
__device__ float g_bc[HH];
// CSR build + permuted edge data
__device__ int g_off[NN + 1];
__device__ int g_cursor[NN];
__device__ int g_tmp[NN];
__device__ int g_bsum[SCAN_B];
__device__ int g_srcp[EE];
__device__ float g_attr8[(size_t)EE * 8];
// bf16 hi/lo split GEMM operands
__device__ __nv_bfloat16 g_Ab[(size_t)NN * 1024];        // A' [M][2K], K<=512
__device__ __nv_bfloat16 g_B1[(size_t)LL * 768 * 512];   // B1' [3K=768][N=512] k-major
__device__ __nv_bfloat16 g_B2[(size_t)LL * 1536 * 256];  // B2' [3K=1536][N=256]

// ================= PTX helpers =================
__device__ __forceinline__ uint32_t smem_u32(const void* p) {
    uint32_t a;
    asm("{ .reg .u64 t; cvta.to.shared.u64 t, %1; cvt.u32.u64 %0, t; }" : "=r"(a) : "l"(p));
    return a;
}
__device__ __forceinline__ void cpa16(uint32_t dst, const void* src, int sz) {
    asm volatile("cp.async.cg.shared.global [%0], [%1], 16, %2;"
                 :: "r"(dst), "l"(src), "r"(sz) : "memory");
}
#define CP_COMMIT() asm volatile("cp.async.commit_group;" ::: "memory")
#define CP_WAIT2()  asm volatile("cp.async.wait_group 2;" ::: "memory")

#define LDSM_X4(r, addr) \
    asm volatile("ldmatrix.sync.aligned.m8n8.x4.shared.b16 {%0,%1,%2,%3}, [%4];" \
        : "=r"((r)[0]), "=r"((r)[1]), "=r"((r)[2]), "=r"((r)[3]) : "r"(addr))
#define LDSM_X4T(r, addr) \
    asm volatile("ldmatrix.sync.aligned.m8n8.x4.trans.shared.b16 {%0,%1,%2,%3}, [%4];" \
        : "=r"((r)[0]), "=r"((r)[1]), "=r"((r)[2]), "=r"((r)[3]) : "r"(addr))
#define MMA16816(d, a, b0, b1) \
    asm volatile("mma.sync.aligned.m16n8k16.row.col.f32.bf16.bf16.f32 " \
        "{%0,%1,%2,%3}, {%4,%5,%6,%7}, {%8,%9}, {%0,%1,%2,%3};" \
        : "+f"((d)[0]), "+f"((d)[1]), "+f"((d)[2]), "+f"((d)[3]) \
        : "r"((a)[0]), "r"((a)[1]), "r"((a)[2]), "r"((a)[3]), "r"(b0), "r"(b1))

// ---------------- init: h = node_emb[x] ----------------
__global__ void k_init_h(const int* __restrict__ x, const float* __restrict__ emb) {
    int i = blockIdx.x;
    int d = threadIdx.x;
    g_h[(size_t)i * DD + d] = emb[(size_t)x[i] * DD + d];
}

// ---------------- CSR build ----------------
__global__ void k_zero_cursor(int M) {
    int i = blockIdx.x * blockDim.x + threadIdx.x;
    if (i < M) g_cursor[i] = 0;
}
__global__ void k_hist(const int* __restrict__ dst, int E) {
    int e = blockIdx.x * blockDim.x + threadIdx.x;
    if (e < E) atomicAdd(&g_cursor[dst[e]], 1);
}
__global__ void k_scan1(int M) {
    __shared__ int s[SCAN_B];
    int t = threadIdx.x;
    int i = blockIdx.x * SCAN_B + t;
    int v = (i < M) ? g_cursor[i] : 0;
    s[t] = v;
    __syncthreads();
    for (int d = 1; d < SCAN_B; d <<= 1) {
        int x = (t >= d) ? s[t - d] : 0;
        __syncthreads();
        s[t] += x;
        __syncthreads();
    }
    if (i < M) g_tmp[i] = s[t];
    if (t == SCAN_B - 1) g_bsum[blockIdx.x] = s[t];
}
__global__ void k_scan2(int NB) {
    __shared__ int s[SCAN_B];
    int t = threadIdx.x;
    int v = (t < NB) ? g_bsum[t] : 0;
    s[t] = v;
    __syncthreads();
    for (int d = 1; d < SCAN_B; d <<= 1) {
        int x = (t >= d) ? s[t - d] : 0;
        __syncthreads();
        s[t] += x;
        __syncthreads();
    }
    if (t < NB) g_bsum[t] = s[t] - v;
}
__global__ void k_scan3(int M) {
    int i = blockIdx.x * SCAN_B + threadIdx.x;
    if (i < M) g_off[i + 1] = g_tmp[i] + g_bsum[blockIdx.x];
    if (i == 0) g_off[0] = 0;
}
__global__ void k_setcur(int M) {
    int i = blockIdx.x * blockDim.x + threadIdx.x;
    if (i < M) g_cursor[i] = g_off[i];
}
__global__ void k_scatter(const int* __restrict__ src, const int* __restrict__ dst,
                          const float* __restrict__ attr, int E) {
    int e = blockIdx.x * blockDim.x + threadIdx.x;
    if (e < E) {
        int p = atomicAdd(&g_cursor[dst[e]], 1);
        g_srcp[p] = src[e];
        const float* at = attr + (size_t)e * 7;
        float* o = g_attr8 + (size_t)p * 8;
        *(float4*)(o) = make_float4(at[0], at[1], at[2], at[3]);
        *(float4*)(o + 4) = make_float4(at[4], at[5], at[6], 0.f);
    }
}

// ---------------- gather ----------------
__global__ void __launch_bounds__(256)
k_gather(const float* __restrict__ We, const float* __restrict__ be, int M) {
    int t = threadIdx.x;
    int cg = (t & 63) * 4;
    int n = blockIdx.x * 4 + (t >> 6);

    float4 w[7];
    #pragma unroll
    for (int k = 0; k < 7; k++) w[k] = *(const float4*)(We + k * DD + cg);
    float4 bev = *(const float4*)(be + cg);

    if (n >= M) return;
    int p0 = g_off[n], p1 = g_off[n + 1];
    float4 acc = make_float4(0.f, 0.f, 0.f, 0.f);
    #pragma unroll 4
    for (int p = p0; p < p1; p++) {
        int s = g_srcp[p];
        float4 a0 = *(const float4*)(g_attr8 + (size_t)p * 8);
        float4 a1 = *(const float4*)(g_attr8 + (size_t)p * 8 + 4);
        float4 hv = *(const float4*)(g_h + (size_t)s * DD + cg);
        float4 emb = bev;
        emb.x = fmaf(a0.x, w[0].x, emb.x); emb.y = fmaf(a0.x, w[0].y, emb.y);
        emb.z = fmaf(a0.x, w[0].z, emb.z); emb.w = fmaf(a0.x, w[0].w, emb.w);
        emb.x = fmaf(a0.y, w[1].x, emb.x); emb.y = fmaf(a0.y, w[1].y, emb.y);
        emb.z = fmaf(a0.y, w[1].z, emb.z); emb.w = fmaf(a0.y, w[1].w, emb.w);
        emb.x = fmaf(a0.z, w[2].x, emb.x); emb.y = fmaf(a0.z, w[2].y, emb.y);
        emb.z = fmaf(a0.z, w[2].z, emb.z); emb.w = fmaf(a0.z, w[2].w, emb.w);
        emb.x = fmaf(a0.w, w[3].x, emb.x); emb.y = fmaf(a0.w, w[3].y, emb.y);
        emb.z = fmaf(a0.w, w[3].z, emb.z); emb.w = fmaf(a0.w, w[3].w, emb.w);
        emb.x = fmaf(a1.x, w[4].x, emb.x); emb.y = fmaf(a1.x, w[4].y, emb.y);
        emb.z = fmaf(a1.x, w[4].z, emb.z); emb.w = fmaf(a1.x, w[4].w, emb.w);
        emb.x = fmaf(a1.y, w[5].x, emb.x); emb.y = fmaf(a1.y, w[5].y, emb.y);
        emb.z = fmaf(a1.y, w[5].z, emb.z); emb.w = fmaf(a1.y, w[5].w, emb.w);
        emb.x = fmaf(a1.z, w[6].x, emb.x); emb.y = fmaf(a1.z, w[6].y, emb.y);
        emb.z = fmaf(a1.z, w[6].z, emb.z); emb.w = fmaf(a1.z, w[6].w, emb.w);
        acc.x += fmaxf(hv.x + emb.x, 0.f);
        acc.y += fmaxf(hv.y + emb.y, 0.f);
        acc.z += fmaxf(hv.z + emb.z, 0.f);
        acc.w += fmaxf(hv.w + emb.w, 0.f);
    }
    *(float4*)(g_agg + (size_t)n * DD + cg) = acc;
}

// ---------------- zero BN stats ----------------
__global__ void k_zero_stats() {
    int i = blockIdx.x * blockDim.x + threadIdx.x;
    if (i < HH) { g_sum[i] = 0.f; g_sumsq[i] = 0.f; }
}

// ---------------- bf16 split converts ----------------
__device__ __forceinline__ uint32_t pk_bf2(float a, float b) {
    __nv_bfloat162 t = __floats2bfloat162_rn(a, b);
    return *(uint32_t*)&t;
}
// A1' = split((1+eps)*h + agg), [M][512] (hi cols 0..255, lo 256..511)
__global__ void k_convA1(const float* __restrict__ eps, int M) {
    int idx = blockIdx.x * 256 + threadIdx.x;
    if (idx >= M * 64) return;
    int row = idx >> 6, k = (idx & 63) * 4;
    float e = 1.f + eps[0];
    size_t off = (size_t)row * DD + k;
    float4 h4 = *(const float4*)(g_h + off);
    float4 a4 = *(const float4*)(g_agg + off);
    float v0 = fmaf(e, h4.x, a4.x), v1 = fmaf(e, h4.y, a4.y);
    float v2 = fmaf(e, h4.z, a4.z), v3 = fmaf(e, h4.w, a4.w);
    float h0 = __bfloat162float(__float2bfloat16(v0));
    float h1 = __bfloat162float(__float2bfloat16(v1));
    float h2 = __bfloat162float(__float2bfloat16(v2));
    float h3 = __bfloat162float(__float2bfloat16(v3));
    uint2 hi = make_uint2(pk_bf2(h0, h1), pk_bf2(h2, h3));
    uint2 lo = make_uint2(pk_bf2(v0 - h0, v1 - h1), pk_bf2(v2 - h2, v3 - h3));
    *(uint2*)(g_Ab + (size_t)row * 512 + k) = hi;
    *(uint2*)(g_Ab + (size_t)row * 512 + 256 + k) = lo;
}
// A2' = split(relu(t1*a + bc)), [M][1024]
__global__ void k_convA2(int M) {
    int idx = blockIdx.x * 256 + threadIdx.x;
    if (idx >= M * 128) return;
    int row = idx >> 7, k = (idx & 127) * 4;
    size_t off = (size_t)row * HH + k;
    float4 t4 = *(const float4*)(g_t1 + off);
    float4 ca = *(const float4*)(g_a + k);
    float4 cb = *(const float4*)(g_bc + k);
    float v0 = fmaxf(fmaf(t4.x, ca.x, cb.x), 0.f);
    float v1 = fmaxf(fmaf(t4.y, ca.y, cb.y), 0.f);
    float v2 = fmaxf(fmaf(t4.z, ca.z, cb.z), 0.f);
    float v3 = fmaxf(fmaf(t4.w, ca.w, cb.w), 0.f);
    float h0 = __bfloat162float(__float2bfloat16(v0));
    float h1 = __bfloat162float(__float2bfloat16(v1));
    float h2 = __bfloat162float(__float2bfloat16(v2));
    float h3 = __bfloat162float(__float2bfloat16(v3));
    uint2 hi = make_uint2(pk_bf2(h0, h1), pk_bf2(h2, h3));
    uint2 lo = make_uint2(pk_bf2(v0 - h0, v1 - h1), pk_bf2(v2 - h2, v3 - h3));
    *(uint2*)(g_Ab + (size_t)row * 1024 + k) = hi;
    *(uint2*)(g_Ab + (size_t)row * 1024 + 512 + k) = lo;
}
// B' k-major: B1 [l][768][512], B2 [l][1536][256]; row blocks: hi, hi, lo
__global__ void k_convB(const float* __restrict__ W1, const float* __restrict__ W2) {
    const int n1 = 768 * 512, n2 = 1536 * 256;
    int idx = blockIdx.x * 256 + threadIdx.x;
    if (idx >= LL * (n1 + n2)) return;
    int l = idx / (n1 + n2);
    int r = idx % (n1 + n2);
    if (r < n1) {
        int kk = r / 512, n = r % 512;
        int part = kk >> 8, k = kk & 255;
        float w = W1[(size_t)l * DD * HH + (size_t)k * HH + n];
        __nv_bfloat16 hi = __float2bfloat16(w);
        g_B1[(size_t)l * n1 + r] =
            (part < 2) ? hi : __float2bfloat16(w - __bfloat162float(hi));
    } else {
        r -= n1;
        int kk = r / 256, n = r % 256;
        int part = kk >> 9, k = kk & 511;
        float w = W2[(size_t)l * HH * DD + (size_t)k * DD + n];
        __nv_bfloat16 hi = __float2bfloat16(w);
        g_B2[(size_t)l * n2 + r] =
            (part < 2) ? hi : __float2bfloat16(w - __bfloat162float(hi));
    }
}

// ---------------- HMMA GEMM: C = A'@B' (3-term split), fused BN stats ----------------
// 128x128x32 tiles, 8 warps (4x2), warp tile 32x64, mma m16n8k16 bf16.
#define AP 80
#define BP 272
#define ASTG 10240
#define BSTG 8704
#define GSMEM (3 * (ASTG + BSTG) + 1024)

template <int NIT, int WRAP, int NC>
__global__ void __launch_bounds__(256)
k_gemm_mma(const __nv_bfloat16* __restrict__ Abase, const __nv_bfloat16* __restrict__ Bbase,
           float* __restrict__ C, int M) {
    extern __shared__ char smem[];
    uint32_t sb = smem_u32(smem);
    uint32_t aB = sb, bB = sb + 3 * ASTG;
    float* ssum = (float*)(smem + 3 * (ASTG + BSTG));
    float* ssq = ssum + 128;

    int tid = threadIdx.x, lane = tid & 31, wid = tid >> 5;
    int wm = wid >> 1, wn = wid & 1;
    int brow = blockIdx.y * 128, bcol = blockIdx.x * 128;

    if (tid < 128) { ssum[tid] = 0.f; ssq[tid] = 0.f; }

    float acc[2][8][4];
    #pragma unroll
    for (int i = 0; i < 2; i++)
        #pragma unroll
        for (int j = 0; j < 8; j++)
            #pragma unroll
            for (int q = 0; q < 4; q++) acc[i][j][q] = 0.f;

    int arow = tid >> 1, ac16 = (tid & 1) * 2;
    int bkr = tid >> 3, bc16 = (tid & 7) * 2;

    auto load = [&](int s, int it) {
        int ac = it * 32; if (ac >= WRAP) ac -= WRAP;
        int ok = (brow + arow < M) ? 16 : 0;
        const char* srcA = (const char*)(Abase + (size_t)(brow + arow) * WRAP + ac);
        uint32_t dA = aB + s * ASTG + arow * AP;
        cpa16(dA + ac16 * 16, srcA + ac16 * 16, ok);
        cpa16(dA + ac16 * 16 + 16, srcA + ac16 * 16 + 16, ok);
        const char* srcB = (const char*)(Bbase + (size_t)(it * 32 + bkr) * NC + bcol);
        uint32_t dB = bB + s * BSTG + bkr * BP;
        cpa16(dB + bc16 * 16, srcB + bc16 * 16, 16);
        cpa16(dB + bc16 * 16 + 16, srcB + bc16 * 16 + 16, 16);
    };

    load(0, 0); CP_COMMIT();
    load(1, 1); CP_COMMIT();

    for (int i = 0; i < NIT; i++) {
        int ls = (i + 2) % 3;
        if (i + 2 < NIT) load(ls, i + 2);
        CP_COMMIT();
        CP_WAIT2();
        __syncthreads();

        int s = i % 3;
        uint32_t ab = aB + s * ASTG, bb = bB + s * BSTG;
        uint32_t a[2][2][4], b[4][2][4];
        #pragma unroll
        for (int mt = 0; mt < 2; mt++)
            #pragma unroll
            for (int kh = 0; kh < 2; kh++)
                LDSM_X4(a[mt][kh],
                        ab + (wm * 32 + mt * 16 + (lane & 15)) * AP +
                             (kh * 16 + (lane >> 4) * 8) * 2);
        #pragma unroll
        for (int nt2 = 0; nt2 < 4; nt2++)
            #pragma unroll
            for (int kh = 0; kh < 2; kh++)
                LDSM_X4T(b[nt2][kh],
                         bb + (kh * 16 + (lane & 15)) * BP +
                              (wn * 64 + nt2 * 16 + (lane >> 4) * 8) * 2);
        #pragma unroll
        for (int mt = 0; mt < 2; mt++)
            #pragma unroll
            for (int nt = 0; nt < 8; nt++) {
                int nt2 = nt >> 1, jj = (nt & 1) * 2;
                MMA16816(acc[mt][nt], a[mt][0], b[nt2][0][jj], b[nt2][0][jj + 1]);
                MMA16816(acc[mt][nt], a[mt][1], b[nt2][1][jj], b[nt2][1][jj + 1]);
            }
        __syncthreads();
    }

    // ---- epilogue: store C + fused BN stats ----
    int r0 = brow + wm * 32 + (lane >> 2);
    int cb = bcol + wn * 64 + (lane & 3) * 2;
    #pragma unroll
    for (int mt = 0; mt < 2; mt++)
        #pragma unroll
        for (int rh = 0; rh < 2; rh++) {
            int row = r0 + mt * 16 + rh * 8;
            if (row < M) {
                float* cr = C + (size_t)row * NC + cb;
                #pragma unroll
                for (int nt = 0; nt < 8; nt++)
                    *(float2*)(cr + nt * 8) =
                        make_float2(acc[mt][nt][rh * 2], acc[mt][nt][rh * 2 + 1]);
            }
        }
    #pragma unroll
    for (int nt = 0; nt < 8; nt++) {
        float s0 = 0.f, s1 = 0.f, q0 = 0.f, q1 = 0.f;
        #pragma unroll
        for (int mt = 0; mt < 2; mt++)
            #pragma unroll
            for (int rh = 0; rh < 2; rh++) {
                if (r0 + mt * 16 + rh * 8 < M) {
                    float v0 = acc[mt][nt][rh * 2], v1 = acc[mt][nt][rh * 2 + 1];
                    s0 += v0; q0 = fmaf(v0, v0, q0);
                    s1 += v1; q1 = fmaf(v1, v1, q1);
                }
            }
        int c = wn * 64 + nt * 8 + (lane & 3) * 2;
        atomicAdd(&ssum[c], s0);
        atomicAdd(&ssum[c + 1], s1);
        atomicAdd(&ssq[c], q0);
        atomicAdd(&ssq[c + 1], q1);
    }
    __syncthreads();
    if (tid < 128) {
        atomicAdd(&g_sum[bcol + tid], ssum[tid]);
        atomicAdd(&g_sumsq[bcol + tid], ssq[tid]);
    }
}

// ---------------- BN finalize ----------------
__global__ void k_bnfin(const float* __restrict__ g, const float* __restrict__ bt, float invM) {
    int c = blockIdx.x * blockDim.x + threadIdx.x;
    float mu = g_sum[c] * invM;
    float var = fmaf(-mu, mu, g_sumsq[c] * invM);
    float a = g[c] * rsqrtf(var + 1e-5f);
    g_a[c] = a;
    g_bc[c] = fmaf(-mu, a, bt[c]);
}

// ---------------- apply BN2 (+relu) ----------------
template <int TO_OUT>
__global__ void k_apply(float* __restrict__ out, int relu) {
    int idx = blockIdx.x * blockDim.x + threadIdx.x;
    float4 v = ((const float4*)g_agg)[idx];
    int c = (idx * 4) & (DD - 1);
    float4 a = *(const float4*)(g_a + c);
    float4 b = *(const float4*)(g_bc + c);
    v.x = fmaf(v.x, a.x, b.x);
    v.y = fmaf(v.y, a.y, b.y);
    v.z = fmaf(v.z, a.z, b.z);
    v.w = fmaf(v.w, a.w, b.w);
    if (relu) {
        v.x = fmaxf(v.x, 0.f); v.y = fmaxf(v.y, 0.f);
        v.z = fmaxf(v.z, 0.f); v.w = fmaxf(v.w, 0.f);
    }
    if (TO_OUT) ((float4*)out)[idx] = v;
    else        ((float4*)g_h)[idx] = v;
}

// ---------------- launcher ----------------
extern "C" void kernel_launch(void* const* d_in, const int* in_sizes, int n_in,
                              void* d_out, int out_size) {
    const int*   x        = (const int*)d_in[0];
    const int*   ei       = (const int*)d_in[1];
    const float* attr     = (const float*)d_in[2];
    const float* node_emb = (const float*)d_in[4];
    const float* We       = (const float*)d_in[5];
    const float* be       = (const float*)d_in[6];
    const float* W1       = (const float*)d_in[7];
    const float* g1       = (const float*)d_in[9];
    const float* bt1      = (const float*)d_in[10];
    const float* W2       = (const float*)d_in[11];
    const float* eps      = (const float*)d_in[13];
    const float* gbn      = (const float*)d_in[14];
    const float* bbn      = (const float*)d_in[15];
    float* out = (float*)d_out;

    int M = in_sizes[0];
    int E = in_sizes[1] / 2;
    const int* dst = ei + E;
    float invM = 1.0f / (float)M;

    // DEVICE addresses of __device__ globals (host-side symbol decay is invalid!)
    void *pAb = nullptr, *pB1 = nullptr, *pB2 = nullptr, *pT1 = nullptr, *pAgg = nullptr;
    cudaGetSymbolAddress(&pAb, g_Ab);
    cudaGetSymbolAddress(&pB1, g_B1);
    cudaGetSymbolAddress(&pB2, g_B2);
    cudaGetSymbolAddress(&pT1, g_t1);
    cudaGetSymbolAddress(&pAgg, g_agg);
    const __nv_bfloat16* dAb = (const __nv_bfloat16*)pAb;
    const __nv_bfloat16* dB1 = (const __nv_bfloat16*)pB1;
    const __nv_bfloat16* dB2 = (const __nv_bfloat16*)pB2;
    float* dT1 = (float*)pT1;
    float* dAgg = (float*)pAgg;

    cudaFuncSetAttribute(k_gemm_mma<24, 512, 512>,
                         cudaFuncAttributeMaxDynamicSharedMemorySize, GSMEM);
    cudaFuncSetAttribute(k_gemm_mma<48, 1024, 256>,
                         cudaFuncAttributeMaxDynamicSharedMemorySize, GSMEM);

    int ewGrid = (M * DD / 4 + 255) / 256;
    int nb = (M + SCAN_B - 1) / SCAN_B;
    int ntm = (M + 127) / 128;
    dim3 g1grid(HH / 128, ntm), g2grid(DD / 128, ntm);

    // ---- CSR build + permute ----
    k_zero_cursor<<<(M + 255) / 256, 256>>>(M);
    k_hist<<<(E + 255) / 256, 256>>>(dst, E);
    k_scan1<<<nb, SCAN_B>>>(M);
    k_scan2<<<1, SCAN_B>>>(nb);
    k_scan3<<<nb, SCAN_B>>>(M);
    k_setcur<<<(M + 255) / 256, 256>>>(M);
    k_scatter<<<(E + 255) / 256, 256>>>(ei, dst, attr, E);

    k_init_h<<<M, 256>>>(x, node_emb);
    k_convB<<<(LL * (768 * 512 + 1536 * 256) + 255) / 256, 256>>>(W1, W2);

    for (int l = 0; l < LL; l++) {
        k_gather<<<(M + 3) / 4, 256>>>(We + (size_t)l * 7 * DD, be + (size_t)l * DD, M);

        k_convA1<<<(M * 64 + 255) / 256, 256>>>(eps + l, M);
        k_zero_stats<<<2, 256>>>();
        k_gemm_mma<24, 512, 512><<<g1grid, 256, GSMEM>>>(
            dAb, dB1 + (size_t)l * 768 * 512, dT1, M);
        k_bnfin<<<HH / 256, 256>>>(g1 + (size_t)l * HH, bt1 + (size_t)l * HH, invM);

        k_convA2<<<(M * 128 + 255) / 256, 256>>>(M);
        k_zero_stats<<<2, 256>>>();
        k_gemm_mma<48, 1024, 256><<<g2grid, 256, GSMEM>>>(
            dAb, dB2 + (size_t)l * 1536 * 256, dAgg, M);
        k_bnfin<<<DD / 256, 256>>>(gbn + (size_t)l * DD, bbn + (size_t)l * DD, invM);

        if (l == LL - 1) k_apply<1><<<ewGrid, 256>>>(out, 0);
        else             k_apply<0><<<ewGrid, 256>>>(out, 1);
    }
}

// round 7
// speedup vs baseline: 1.3321x; 1.0140x over previous
#include <cuda_runtime.h>
#include <cuda_bf16.h>
#include <math.h>
#include <stdint.h>

#define NN 100000
#define EE 1600000
#define DD 256
#define HH 512
#define LL 5
#define SCAN_B 512

// ---------------- device scratch (no allocs allowed) ----------------
__device__ float g_h[(size_t)NN * DD];
__device__ float g_agg[(size_t)NN * DD];       // z2 buffer (GEMM2 out)
__device__ float g_t1[(size_t)NN * HH];
__device__ float g_sum[HH];
__device__ float g_sumsq[HH];
__device__ float g_a[HH];
__device__ float g_bc[HH];
// CSR build + permuted edge data
__device__ int g_off[NN + 1];
__device__ int g_cursor[NN];
__device__ int g_tmp[NN];
__device__ int g_bsum[SCAN_B];
__device__ int g_srcp[EE];
__device__ float g_attr8[(size_t)EE * 8];
// bf16 hi/lo split GEMM operands
__device__ __nv_bfloat16 g_Ab[(size_t)NN * 1024];        // A' [M][2K], K<=512
__device__ __nv_bfloat16 g_B1[(size_t)LL * 768 * 512];   // B1' [3K=768][N=512] k-major
__device__ __nv_bfloat16 g_B2[(size_t)LL * 1536 * 256];  // B2' [3K=1536][N=256]

// ================= PTX helpers =================
__device__ __forceinline__ uint32_t smem_u32(const void* p) {
    uint32_t a;
    asm("{ .reg .u64 t; cvta.to.shared.u64 t, %1; cvt.u32.u64 %0, t; }" : "=r"(a) : "l"(p));
    return a;
}
__device__ __forceinline__ void cpa16(uint32_t dst, const void* src, int sz) {
    asm volatile("cp.async.cg.shared.global [%0], [%1], 16, %2;"
                 :: "r"(dst), "l"(src), "r"(sz) : "memory");
}
#define CP_COMMIT() asm volatile("cp.async.commit_group;" ::: "memory")
#define CP_WAIT1()  asm volatile("cp.async.wait_group 1;" ::: "memory")

#define LDSM_X4(r, addr) \
    asm volatile("ldmatrix.sync.aligned.m8n8.x4.shared.b16 {%0,%1,%2,%3}, [%4];" \
        : "=r"((r)[0]), "=r"((r)[1]), "=r"((r)[2]), "=r"((r)[3]) : "r"(addr))
#define LDSM_X4T(r, addr) \
    asm volatile("ldmatrix.sync.aligned.m8n8.x4.trans.shared.b16 {%0,%1,%2,%3}, [%4];" \
        : "=r"((r)[0]), "=r"((r)[1]), "=r"((r)[2]), "=r"((r)[3]) : "r"(addr))
#define MMA16816(d, a, b0, b1) \
    asm volatile("mma.sync.aligned.m16n8k16.row.col.f32.bf16.bf16.f32 " \
        "{%0,%1,%2,%3}, {%4,%5,%6,%7}, {%8,%9}, {%0,%1,%2,%3};" \
        : "+f"((d)[0]), "+f"((d)[1]), "+f"((d)[2]), "+f"((d)[3]) \
        : "r"((a)[0]), "r"((a)[1]), "r"((a)[2]), "r"((a)[3]), "r"(b0), "r"(b1))

// ---------------- init: h = node_emb[x] ----------------
__global__ void k_init_h(const int* __restrict__ x, const float* __restrict__ emb) {
    int i = blockIdx.x;
    int d = threadIdx.x;
    g_h[(size_t)i * DD + d] = emb[(size_t)x[i] * DD + d];
}

// ---------------- CSR build ----------------
__global__ void k_zero_cursor(int M) {
    int i = blockIdx.x * blockDim.x + threadIdx.x;
    if (i < M) g_cursor[i] = 0;
}
__global__ void k_hist(const int* __restrict__ dst, int E) {
    int e = blockIdx.x * blockDim.x + threadIdx.x;
    if (e < E) atomicAdd(&g_cursor[dst[e]], 1);
}
__global__ void k_scan1(int M) {
    __shared__ int s[SCAN_B];
    int t = threadIdx.x;
    int i = blockIdx.x * SCAN_B + t;
    int v = (i < M) ? g_cursor[i] : 0;
    s[t] = v;
    __syncthreads();
    for (int d = 1; d < SCAN_B; d <<= 1) {
        int x = (t >= d) ? s[t - d] : 0;
        __syncthreads();
        s[t] += x;
        __syncthreads();
    }
    if (i < M) g_tmp[i] = s[t];
    if (t == SCAN_B - 1) g_bsum[blockIdx.x] = s[t];
}
__global__ void k_scan2(int NB) {
    __shared__ int s[SCAN_B];
    int t = threadIdx.x;
    int v = (t < NB) ? g_bsum[t] : 0;
    s[t] = v;
    __syncthreads();
    for (int d = 1; d < SCAN_B; d <<= 1) {
        int x = (t >= d) ? s[t - d] : 0;
        __syncthreads();
        s[t] += x;
        __syncthreads();
    }
    if (t < NB) g_bsum[t] = s[t] - v;
}
__global__ void k_scan3(int M) {
    int i = blockIdx.x * SCAN_B + threadIdx.x;
    if (i < M) g_off[i + 1] = g_tmp[i] + g_bsum[blockIdx.x];
    if (i == 0) g_off[0] = 0;
}
__global__ void k_setcur(int M) {
    int i = blockIdx.x * blockDim.x + threadIdx.x;
    if (i < M) g_cursor[i] = g_off[i];
}
__global__ void k_scatter(const int* __restrict__ src, const int* __restrict__ dst,
                          const float* __restrict__ attr, int E) {
    int e = blockIdx.x * blockDim.x + threadIdx.x;
    if (e < E) {
        int p = atomicAdd(&g_cursor[dst[e]], 1);
        g_srcp[p] = src[e];
        const float* at = attr + (size_t)e * 7;
        float* o = g_attr8 + (size_t)p * 8;
        *(float4*)(o) = make_float4(at[0], at[1], at[2], at[3]);
        *(float4*)(o + 4) = make_float4(at[4], at[5], at[6], 0.f);
    }
}

// ---------------- bf16 pack ----------------
__device__ __forceinline__ uint32_t pk_bf2(float a, float b) {
    __nv_bfloat162 t = __floats2bfloat162_rn(a, b);
    return *(uint32_t*)&t;
}

// ---------------- gather (+ fused A1' split-convert) ----------------
// A1'[n] = split_bf16( (1+eps)*h[n] + sum_{e in CSR[n]} relu(h[src]+attr@We+be) )
__global__ void __launch_bounds__(256)
k_gather(const float* __restrict__ We, const float* __restrict__ be,
         const float* __restrict__ eps, int M) {
    int t = threadIdx.x;
    int cg = (t & 63) * 4;
    int n = blockIdx.x * 4 + (t >> 6);

    float4 w[7];
    #pragma unroll
    for (int k = 0; k < 7; k++) w[k] = *(const float4*)(We + k * DD + cg);
    float4 bev = *(const float4*)(be + cg);
    float e1 = 1.f + eps[0];

    if (n >= M) return;
    int p0 = g_off[n], p1 = g_off[n + 1];
    float4 acc = make_float4(0.f, 0.f, 0.f, 0.f);
    #pragma unroll 4
    for (int p = p0; p < p1; p++) {
        int s = g_srcp[p];
        float4 a0 = *(const float4*)(g_attr8 + (size_t)p * 8);
        float4 a1 = *(const float4*)(g_attr8 + (size_t)p * 8 + 4);
        float4 hv = *(const float4*)(g_h + (size_t)s * DD + cg);
        float4 emb = bev;
        emb.x = fmaf(a0.x, w[0].x, emb.x); emb.y = fmaf(a0.x, w[0].y, emb.y);
        emb.z = fmaf(a0.x, w[0].z, emb.z); emb.w = fmaf(a0.x, w[0].w, emb.w);
        emb.x = fmaf(a0.y, w[1].x, emb.x); emb.y = fmaf(a0.y, w[1].y, emb.y);
        emb.z = fmaf(a0.y, w[1].z, emb.z); emb.w = fmaf(a0.y, w[1].w, emb.w);
        emb.x = fmaf(a0.z, w[2].x, emb.x); emb.y = fmaf(a0.z, w[2].y, emb.y);
        emb.z = fmaf(a0.z, w[2].z, emb.z); emb.w = fmaf(a0.z, w[2].w, emb.w);
        emb.x = fmaf(a0.w, w[3].x, emb.x); emb.y = fmaf(a0.w, w[3].y, emb.y);
        emb.z = fmaf(a0.w, w[3].z, emb.z); emb.w = fmaf(a0.w, w[3].w, emb.w);
        emb.x = fmaf(a1.x, w[4].x, emb.x); emb.y = fmaf(a1.x, w[4].y, emb.y);
        emb.z = fmaf(a1.x, w[4].z, emb.z); emb.w = fmaf(a1.x, w[4].w, emb.w);
        emb.x = fmaf(a1.y, w[5].x, emb.x); emb.y = fmaf(a1.y, w[5].y, emb.y);
        emb.z = fmaf(a1.y, w[5].z, emb.z); emb.w = fmaf(a1.y, w[5].w, emb.w);
        emb.x = fmaf(a1.z, w[6].x, emb.x); emb.y = fmaf(a1.z, w[6].y, emb.y);
        emb.z = fmaf(a1.z, w[6].z, emb.z); emb.w = fmaf(a1.z, w[6].w, emb.w);
        acc.x += fmaxf(hv.x + emb.x, 0.f);
        acc.y += fmaxf(hv.y + emb.y, 0.f);
        acc.z += fmaxf(hv.z + emb.z, 0.f);
        acc.w += fmaxf(hv.w + emb.w, 0.f);
    }
    // fused: v = (1+eps)*h[n] + acc, split to bf16 hi/lo into A1' [M][512]
    float4 hn = *(const float4*)(g_h + (size_t)n * DD + cg);
    float v0 = fmaf(e1, hn.x, acc.x), v1 = fmaf(e1, hn.y, acc.y);
    float v2 = fmaf(e1, hn.z, acc.z), v3 = fmaf(e1, hn.w, acc.w);
    float h0 = __bfloat162float(__float2bfloat16(v0));
    float h1 = __bfloat162float(__float2bfloat16(v1));
    float h2 = __bfloat162float(__float2bfloat16(v2));
    float h3 = __bfloat162float(__float2bfloat16(v3));
    uint2 hi = make_uint2(pk_bf2(h0, h1), pk_bf2(h2, h3));
    uint2 lo = make_uint2(pk_bf2(v0 - h0, v1 - h1), pk_bf2(v2 - h2, v3 - h3));
    *(uint2*)(g_Ab + (size_t)n * 512 + cg) = hi;
    *(uint2*)(g_Ab + (size_t)n * 512 + 256 + cg) = lo;
}

// ---------------- zero BN stats ----------------
__global__ void k_zero_stats() {
    int i = blockIdx.x * blockDim.x + threadIdx.x;
    if (i < HH) { g_sum[i] = 0.f; g_sumsq[i] = 0.f; }
}

// A2' = split(relu(t1*a + bc)), [M][1024]
__global__ void k_convA2(int M) {
    int idx = blockIdx.x * 256 + threadIdx.x;
    if (idx >= M * 128) return;
    int row = idx >> 7, k = (idx & 127) * 4;
    size_t off = (size_t)row * HH + k;
    float4 t4 = *(const float4*)(g_t1 + off);
    float4 ca = *(const float4*)(g_a + k);
    float4 cb = *(const float4*)(g_bc + k);
    float v0 = fmaxf(fmaf(t4.x, ca.x, cb.x), 0.f);
    float v1 = fmaxf(fmaf(t4.y, ca.y, cb.y), 0.f);
    float v2 = fmaxf(fmaf(t4.z, ca.z, cb.z), 0.f);
    float v3 = fmaxf(fmaf(t4.w, ca.w, cb.w), 0.f);
    float h0 = __bfloat162float(__float2bfloat16(v0));
    float h1 = __bfloat162float(__float2bfloat16(v1));
    float h2 = __bfloat162float(__float2bfloat16(v2));
    float h3 = __bfloat162float(__float2bfloat16(v3));
    uint2 hi = make_uint2(pk_bf2(h0, h1), pk_bf2(h2, h3));
    uint2 lo = make_uint2(pk_bf2(v0 - h0, v1 - h1), pk_bf2(v2 - h2, v3 - h3));
    *(uint2*)(g_Ab + (size_t)row * 1024 + k) = hi;
    *(uint2*)(g_Ab + (size_t)row * 1024 + 512 + k) = lo;
}
// B' k-major: B1 [l][768][512], B2 [l][1536][256]; row blocks: hi, hi, lo
__global__ void k_convB(const float* __restrict__ W1, const float* __restrict__ W2) {
    const int n1 = 768 * 512, n2 = 1536 * 256;
    int idx = blockIdx.x * 256 + threadIdx.x;
    if (idx >= LL * (n1 + n2)) return;
    int l = idx / (n1 + n2);
    int r = idx % (n1 + n2);
    if (r < n1) {
        int kk = r / 512, n = r % 512;
        int part = kk >> 8, k = kk & 255;
        float w = W1[(size_t)l * DD * HH + (size_t)k * HH + n];
        __nv_bfloat16 hi = __float2bfloat16(w);
        g_B1[(size_t)l * n1 + r] =
            (part < 2) ? hi : __float2bfloat16(w - __bfloat162float(hi));
    } else {
        r -= n1;
        int kk = r / 256, n = r % 256;
        int part = kk >> 9, k = kk & 511;
        float w = W2[(size_t)l * HH * DD + (size_t)k * DD + n];
        __nv_bfloat16 hi = __float2bfloat16(w);
        g_B2[(size_t)l * n2 + r] =
            (part < 2) ? hi : __float2bfloat16(w - __bfloat162float(hi));
    }
}

// ---------------- HMMA GEMM: C = A'@B' (3-term split), fused BN stats ----------------
// 128x128x32 tiles, 8 warps (4x2), warp tile 32x64, single-sync 3-stage pipeline.
#define AP 80
#define BP 272
#define ASTG 10240
#define BSTG 8704
#define GSMEM (3 * (ASTG + BSTG) + 1024)

template <int NIT, int WRAP, int NC>
__global__ void __launch_bounds__(256)
k_gemm_mma(const __nv_bfloat16* __restrict__ Abase, const __nv_bfloat16* __restrict__ Bbase,
           float* __restrict__ C, int M) {
    extern __shared__ char smem[];
    uint32_t sb = smem_u32(smem);
    uint32_t aB = sb, bB = sb + 3 * ASTG;
    float* ssum = (float*)(smem + 3 * (ASTG + BSTG));
    float* ssq = ssum + 128;

    int tid = threadIdx.x, lane = tid & 31, wid = tid >> 5;
    int wm = wid >> 1, wn = wid & 1;
    int brow = blockIdx.y * 128, bcol = blockIdx.x * 128;

    if (tid < 128) { ssum[tid] = 0.f; ssq[tid] = 0.f; }

    float acc[2][8][4];
    #pragma unroll
    for (int i = 0; i < 2; i++)
        #pragma unroll
        for (int j = 0; j < 8; j++)
            #pragma unroll
            for (int q = 0; q < 4; q++) acc[i][j][q] = 0.f;

    int arow = tid >> 1, ac16 = (tid & 1) * 2;
    int bkr = tid >> 3, bc16 = (tid & 7) * 2;

    auto load = [&](int s, int it) {
        int ac = it * 32; if (ac >= WRAP) ac -= WRAP;
        int ok = (brow + arow < M) ? 16 : 0;
        const char* srcA = (const char*)(Abase + (size_t)(brow + arow) * WRAP + ac);
        uint32_t dA = aB + s * ASTG + arow * AP;
        cpa16(dA + ac16 * 16, srcA + ac16 * 16, ok);
        cpa16(dA + ac16 * 16 + 16, srcA + ac16 * 16 + 16, ok);
        const char* srcB = (const char*)(Bbase + (size_t)(it * 32 + bkr) * NC + bcol);
        uint32_t dB = bB + s * BSTG + bkr * BP;
        cpa16(dB + bc16 * 16, srcB + bc16 * 16, 16);
        cpa16(dB + bc16 * 16 + 16, srcB + bc16 * 16 + 16, 16);
    };

    load(0, 0); CP_COMMIT();
    load(1, 1); CP_COMMIT();

    for (int i = 0; i < NIT; i++) {
        CP_WAIT1();          // stage i%3 data arrived (my part)
        __syncthreads();     // all threads' stage-i data visible; all done reading stage (i+2)%3
        if (i + 2 < NIT) load((i + 2) % 3, i + 2);
        CP_COMMIT();         // keep group numbering consistent (empty group ok)

        int s = i % 3;
        uint32_t ab = aB + s * ASTG, bb = bB + s * BSTG;
        uint32_t a[2][2][4], b[4][2][4];
        #pragma unroll
        for (int mt = 0; mt < 2; mt++)
            #pragma unroll
            for (int kh = 0; kh < 2; kh++)
                LDSM_X4(a[mt][kh],
                        ab + (wm * 32 + mt * 16 + (lane & 15)) * AP +
                             (kh * 16 + (lane >> 4) * 8) * 2);
        #pragma unroll
        for (int nt2 = 0; nt2 < 4; nt2++)
            #pragma unroll
            for (int kh = 0; kh < 2; kh++)
                LDSM_X4T(b[nt2][kh],
                         bb + (kh * 16 + (lane & 15)) * BP +
                              (wn * 64 + nt2 * 16 + (lane >> 4) * 8) * 2);
        #pragma unroll
        for (int mt = 0; mt < 2; mt++)
            #pragma unroll
            for (int nt = 0; nt < 8; nt++) {
                int nt2 = nt >> 1, jj = (nt & 1) * 2;
                MMA16816(acc[mt][nt], a[mt][0], b[nt2][0][jj], b[nt2][0][jj + 1]);
                MMA16816(acc[mt][nt], a[mt][1], b[nt2][1][jj], b[nt2][1][jj + 1]);
            }
    }
    __syncthreads();

    // ---- epilogue: store C + fused BN stats ----
    int r0 = brow + wm * 32 + (lane >> 2);
    int cb = bcol + wn * 64 + (lane & 3) * 2;
    #pragma unroll
    for (int mt = 0; mt < 2; mt++)
        #pragma unroll
        for (int rh = 0; rh < 2; rh++) {
            int row = r0 + mt * 16 + rh * 8;
            if (row < M) {
                float* cr = C + (size_t)row * NC + cb;
                #pragma unroll
                for (int nt = 0; nt < 8; nt++)
                    *(float2*)(cr + nt * 8) =
                        make_float2(acc[mt][nt][rh * 2], acc[mt][nt][rh * 2 + 1]);
            }
        }
    #pragma unroll
    for (int nt = 0; nt < 8; nt++) {
        float s0 = 0.f, s1 = 0.f, q0 = 0.f, q1 = 0.f;
        #pragma unroll
        for (int mt = 0; mt < 2; mt++)
            #pragma unroll
            for (int rh = 0; rh < 2; rh++) {
                if (r0 + mt * 16 + rh * 8 < M) {
                    float v0 = acc[mt][nt][rh * 2], v1 = acc[mt][nt][rh * 2 + 1];
                    s0 += v0; q0 = fmaf(v0, v0, q0);
                    s1 += v1; q1 = fmaf(v1, v1, q1);
                }
            }
        int c = wn * 64 + nt * 8 + (lane & 3) * 2;
        atomicAdd(&ssum[c], s0);
        atomicAdd(&ssum[c + 1], s1);
        atomicAdd(&ssq[c], q0);
        atomicAdd(&ssq[c + 1], q1);
    }
    __syncthreads();
    if (tid < 128) {
        atomicAdd(&g_sum[bcol + tid], ssum[tid]);
        atomicAdd(&g_sumsq[bcol + tid], ssq[tid]);
    }
}

// ---------------- BN finalize ----------------
__global__ void k_bnfin(const float* __restrict__ g, const float* __restrict__ bt, float invM) {
    int c = blockIdx.x * blockDim.x + threadIdx.x;
    float mu = g_sum[c] * invM;
    float var = fmaf(-mu, mu, g_sumsq[c] * invM);
    float a = g[c] * rsqrtf(var + 1e-5f);
    g_a[c] = a;
    g_bc[c] = fmaf(-mu, a, bt[c]);
}

// ---------------- apply BN2 (+relu) ----------------
template <int TO_OUT>
__global__ void k_apply(float* __restrict__ out, int relu) {
    int idx = blockIdx.x * blockDim.x + threadIdx.x;
    float4 v = ((const float4*)g_agg)[idx];
    int c = (idx * 4) & (DD - 1);
    float4 a = *(const float4*)(g_a + c);
    float4 b = *(const float4*)(g_bc + c);
    v.x = fmaf(v.x, a.x, b.x);
    v.y = fmaf(v.y, a.y, b.y);
    v.z = fmaf(v.z, a.z, b.z);
    v.w = fmaf(v.w, a.w, b.w);
    if (relu) {
        v.x = fmaxf(v.x, 0.f); v.y = fmaxf(v.y, 0.f);
        v.z = fmaxf(v.z, 0.f); v.w = fmaxf(v.w, 0.f);
    }
    if (TO_OUT) ((float4*)out)[idx] = v;
    else        ((float4*)g_h)[idx] = v;
}

// ---------------- launcher ----------------
extern "C" void kernel_launch(void* const* d_in, const int* in_sizes, int n_in,
                              void* d_out, int out_size) {
    const int*   x        = (const int*)d_in[0];
    const int*   ei       = (const int*)d_in[1];
    const float* attr     = (const float*)d_in[2];
    const float* node_emb = (const float*)d_in[4];
    const float* We       = (const float*)d_in[5];
    const float* be       = (const float*)d_in[6];
    const float* W1       = (const float*)d_in[7];
    const float* g1       = (const float*)d_in[9];
    const float* bt1      = (const float*)d_in[10];
    const float* W2       = (const float*)d_in[11];
    const float* eps      = (const float*)d_in[13];
    const float* gbn      = (const float*)d_in[14];
    const float* bbn      = (const float*)d_in[15];
    float* out = (float*)d_out;

    int M = in_sizes[0];
    int E = in_sizes[1] / 2;
    const int* dst = ei + E;
    float invM = 1.0f / (float)M;

    // DEVICE addresses of __device__ globals
    void *pAb = nullptr, *pB1 = nullptr, *pB2 = nullptr, *pT1 = nullptr, *pAgg = nullptr;
    cudaGetSymbolAddress(&pAb, g_Ab);
    cudaGetSymbolAddress(&pB1, g_B1);
    cudaGetSymbolAddress(&pB2, g_B2);
    cudaGetSymbolAddress(&pT1, g_t1);
    cudaGetSymbolAddress(&pAgg, g_agg);
    const __nv_bfloat16* dAb = (const __nv_bfloat16*)pAb;
    const __nv_bfloat16* dB1 = (const __nv_bfloat16*)pB1;
    const __nv_bfloat16* dB2 = (const __nv_bfloat16*)pB2;
    float* dT1 = (float*)pT1;
    float* dAgg = (float*)pAgg;

    cudaFuncSetAttribute(k_gemm_mma<24, 512, 512>,
                         cudaFuncAttributeMaxDynamicSharedMemorySize, GSMEM);
    cudaFuncSetAttribute(k_gemm_mma<48, 1024, 256>,
                         cudaFuncAttributeMaxDynamicSharedMemorySize, GSMEM);

    int ewGrid = (M * DD / 4 + 255) / 256;
    int nb = (M + SCAN_B - 1) / SCAN_B;
    int ntm = (M + 127) / 128;
    dim3 g1grid(HH / 128, ntm), g2grid(DD / 128, ntm);

    // ---- CSR build + permute ----
    k_zero_cursor<<<(M + 255) / 256, 256>>>(M);
    k_hist<<<(E + 255) / 256, 256>>>(dst, E);
    k_scan1<<<nb, SCAN_B>>>(M);
    k_scan2<<<1, SCAN_B>>>(nb);
    k_scan3<<<nb, SCAN_B>>>(M);
    k_setcur<<<(M + 255) / 256, 256>>>(M);
    k_scatter<<<(E + 255) / 256, 256>>>(ei, dst, attr, E);

    k_init_h<<<M, 256>>>(x, node_emb);
    k_convB<<<(LL * (768 * 512 + 1536 * 256) + 255) / 256, 256>>>(W1, W2);

    for (int l = 0; l < LL; l++) {
        // gather + fused A1' convert
        k_gather<<<(M + 3) / 4, 256>>>(We + (size_t)l * 7 * DD, be + (size_t)l * DD,
                                       eps + l, M);

        k_zero_stats<<<2, 256>>>();
        k_gemm_mma<24, 512, 512><<<g1grid, 256, GSMEM>>>(
            dAb, dB1 + (size_t)l * 768 * 512, dT1, M);
        k_bnfin<<<HH / 256, 256>>>(g1 + (size_t)l * HH, bt1 + (size_t)l * HH, invM);

        k_convA2<<<(M * 128 + 255) / 256, 256>>>(M);
        k_zero_stats<<<2, 256>>>();
        k_gemm_mma<48, 1024, 256><<<g2grid, 256, GSMEM>>>(
            dAb, dB2 + (size_t)l * 1536 * 256, dAgg, M);
        k_bnfin<<<DD / 256, 256>>>(gbn + (size_t)l * DD, bbn + (size_t)l * DD, invM);

        if (l == LL - 1) k_apply<1><<<ewGrid, 256>>>(out, 0);
        else             k_apply<0><<<ewGrid, 256>>>(out, 1);
    }
}